// round 4
// baseline (speedup 1.0000x reference)
#include <cuda_runtime.h>
#include <cstdint>

// ============================================================================
// ConvAConnect: per-sample perturbed 3x3 SAME conv, B=32 H=W=64 Cin=128 F=256
// Implicit GEMM per sample: [4096 x 1152] x [1152 x 256], tf32 mma.sync.
// compute_103 target (no 'a'): tcgen05/TMA unavailable -> Ampere-style MMA.
// R4: A and B both staged through a 4-deep cp.async smem pipeline.
// ============================================================================
static constexpr int BATCH = 32;
static constexpr int CIN   = 128;
static constexpr int FOUT  = 256;
static constexpr int NK8   = 144;   // K=1152 / 8
static constexpr int NCHUNK = 36;   // K / 32
static constexpr int NSTAGE = 4;

// Per-sample weights, tf32-rounded, in mma.sync B-fragment order:
// float index = ((b*144 + k8)*4 + wn)*512 + q*128 + lane*4 + jp*2 + slot
//   wn = f>>6, j = (f>>3)&7, q = j>>1, jp = j&1,
//   lane = (f&7)*4 + (k&3), slot = (k>>2)&1.
// Per (k8,wn,q): 512B contiguous = one conflict-free warp LDS.128.
__device__ __align__(256) float g_wfrag[(size_t)BATCH * NK8 * 2048];

// dynamic smem layout (bytes)
static constexpr uint32_t ASTAGE = 16384;                 // 128 rows x 128B
static constexpr uint32_t BSTAGE = 32768;                 // 4 k8 x 2048 floats
static constexpr uint32_t OFF_A  = 0;                     // 4 x 16KB
static constexpr uint32_t OFF_B  = NSTAGE * ASTAGE;       // 65536, 4 x 32KB
static constexpr uint32_t OFF_MB = OFF_B + NSTAGE * BSTAGE;  // 196608
static constexpr uint32_t SMEM_TOTAL = OFF_MB + 1024;     // 197632

__device__ __forceinline__ uint32_t smem_u32(const void* p) {
    uint32_t a;
    asm("{ .reg .u64 t; cvta.to.shared.u64 t, %1; cvt.u32.u64 %0, t; }" : "=r"(a) : "l"(p));
    return a;
}
__device__ __forceinline__ uint32_t to_tf32(float x) {
    uint32_t u;
    asm("cvt.rna.tf32.f32 %0, %1;" : "=r"(u) : "f"(x));
    return u;
}

// ============================================================================
// Prep: g_wfrag = frag_order(tf32(W * Werr[b])). One block per (b, pos).
// ============================================================================
__global__ void __launch_bounds__(256) prep_wfrag(const float* __restrict__ W,
                                                  const float* __restrict__ Werr) {
    __shared__ float4 st4[512];                   // 2048 floats = one k8 slab
    uint32_t* st = (uint32_t*)st4;
    int blk = blockIdx.x;
    int b = blk / 9, pos = blk % 9;
    int f = threadIdx.x;                          // 0..255
    const float* wb = W    + (size_t)pos * CIN * FOUT + f;
    const float* eb = Werr + (size_t)(b * 9 + pos) * CIN * FOUT + f;
    int wn = f >> 6, j = (f >> 3) & 7;
    int q = j >> 1, jp = j & 1;

    for (int cb = 0; cb < 16; cb++) {             // 16 k8 blocks per pos
        __syncthreads();
#pragma unroll
        for (int ci = 0; ci < 8; ci++) {
            int c = cb * 8 + ci;
            float v = wb[(size_t)c * FOUT] * eb[(size_t)c * FOUT];
            int lane = (f & 7) * 4 + (ci & 3);
            st[wn * 512 + q * 128 + lane * 4 + jp * 2 + (ci >> 2)] = to_tf32(v);
        }
        __syncthreads();
        int g = pos * 16 + cb;
        float4* dst = (float4*)(g_wfrag + (size_t)(b * NK8 + g) * 2048);
        dst[f * 2]     = st4[f * 2];
        dst[f * 2 + 1] = st4[f * 2 + 1];
    }
}

// ============================================================================
// Main: 1024 CTAs = 32 samples x 32 M-blocks (128 pixels each). 256 threads.
// 8 warps: wm = wid&1 (M half), wn = wid>>1 (N quarter); warp tile 64x64.
// 4-stage cp.async pipeline carrying both A (swizzled) and B (frag-ordered).
// ============================================================================
__global__ void __launch_bounds__(256, 1)
conv_main(const float* __restrict__ X, const float* __restrict__ bias,
          const float* __restrict__ Berr, float* __restrict__ out) {
    extern __shared__ char smem[];
    const uint32_t sbase = smem_u32(smem);

    const int t = threadIdx.x, l = t & 31, wid = t >> 5;
    const int b = blockIdx.x >> 5, mb = blockIdx.x & 31;
    const int wm = wid & 1, wn = wid >> 1;

    float* sMB = (float*)(smem + OFF_MB);
    sMB[t] = bias[t] * Berr[b * FOUT + t];

    // ---- A producer mapping: thread t covers row t/2, 4 x 16B segs ----
    const int arow = t >> 1;
    const uint32_t aseg0 = (uint32_t)((t & 1) * 4);
    // ---- B producer: straight contiguous 32KB copy, 8 x 16B per thread ----
    const float4* bsrc_base = (const float4*)g_wfrag + (size_t)b * NK8 * 512;

    auto issueStage = [&](int s) {
        int stage = s & (NSTAGE - 1);
        // A tile
        {
            int pos = s >> 2, cb = s & 3;
            int kh = pos / 3, kw = pos % 3;
            int y = mb * 2 + (arow >> 6) + kh - 1;
            int x = (arow & 63) + kw - 1;
            bool valid = ((unsigned)y < 64u) && ((unsigned)x < 64u);
            const float* src = X + (((size_t)b * 64 + (valid ? y : 0)) * 64 +
                                    (valid ? x : 0)) * CIN + cb * 32;
            int sz = valid ? 16 : 0;
            uint32_t dbase = sbase + OFF_A + (uint32_t)stage * ASTAGE +
                             (uint32_t)arow * 128u;
            uint32_t sw = (uint32_t)((arow & 7) << 4);
#pragma unroll
            for (int jj = 0; jj < 4; jj++) {
                uint32_t seg = aseg0 + (uint32_t)jj;
                uint32_t d = dbase + ((seg * 16u) ^ sw);
                asm volatile("cp.async.cg.shared.global [%0], [%1], 16, %2;"
                             :: "r"(d), "l"(src + seg * 4), "r"(sz) : "memory");
            }
        }
        // B tile: g_wfrag[b][s*4 .. s*4+3][...] = 2048 float4 contiguous
        {
            const float4* src = bsrc_base + (size_t)s * 2048;
            uint32_t dbase = sbase + OFF_B + (uint32_t)stage * BSTAGE;
#pragma unroll
            for (int jj = 0; jj < 8; jj++) {
                uint32_t idx = (uint32_t)t + (uint32_t)jj * 256u;
                asm volatile("cp.async.cg.shared.global [%0], [%1], 16;"
                             :: "r"(dbase + idx * 16u), "l"(src + idx) : "memory");
            }
        }
        asm volatile("cp.async.commit_group;" ::: "memory");
    };

    float acc[4][8][4];
#pragma unroll
    for (int mt = 0; mt < 4; mt++)
#pragma unroll
        for (int nt = 0; nt < 8; nt++)
#pragma unroll
            for (int qq = 0; qq < 4; qq++) acc[mt][nt][qq] = 0.f;

    // Prologue: fill 3 stages
    issueStage(0);
    issueStage(1);
    issueStage(2);

    for (int s = 0; s < NCHUNK; s++) {
        if (s + 2 < NCHUNK)
            asm volatile("cp.async.wait_group 2;" ::: "memory");
        else
            asm volatile("cp.async.wait_group 0;" ::: "memory");
        __syncthreads();
        if (s + 3 < NCHUNK) issueStage(s + 3);

        const int stage = s & (NSTAGE - 1);
        const uint32_t stA = sbase + OFF_A + (uint32_t)stage * ASTAGE;
        const uint32_t stB = sbase + OFF_B + (uint32_t)stage * BSTAGE +
                             (uint32_t)wn * 2048u + (uint32_t)l * 16u;

#pragma unroll
        for (int kk = 0; kk < 4; kk++) {
            // B fragments: 4 conflict-free LDS.128 (512B contiguous per warp)
            uint32_t bq[4][4];
            const uint32_t bk = stB + (uint32_t)kk * 8192u;
#pragma unroll
            for (int qq = 0; qq < 4; qq++) {
                asm volatile("ld.shared.v4.b32 {%0,%1,%2,%3}, [%4];"
                             : "=r"(bq[qq][0]), "=r"(bq[qq][1]),
                               "=r"(bq[qq][2]), "=r"(bq[qq][3])
                             : "r"(bk + (uint32_t)qq * 512u));
            }

            // A fragments (swizzled LDS.32) + tf32 round
            uint32_t a[4][4];
            const uint32_t kb0 = (uint32_t)((kk * 8 + (l & 3)) * 4);
#pragma unroll
            for (int mt = 0; mt < 4; mt++) {
                int r = wm * 64 + mt * 16 + (l >> 2);
                uint32_t sw = (uint32_t)((r & 7) << 4);
                uint32_t base = stA + (uint32_t)r * 128u;
                uint32_t ad0 = base + (kb0 ^ sw);
                uint32_t ad2 = base + ((kb0 + 16u) ^ sw);
                float f0, f1, f2, f3;
                asm volatile("ld.shared.f32 %0, [%1];" : "=f"(f0) : "r"(ad0));
                asm volatile("ld.shared.f32 %0, [%1];" : "=f"(f1) : "r"(ad0 + 1024u));
                asm volatile("ld.shared.f32 %0, [%1];" : "=f"(f2) : "r"(ad2));
                asm volatile("ld.shared.f32 %0, [%1];" : "=f"(f3) : "r"(ad2 + 1024u));
                a[mt][0] = to_tf32(f0);
                a[mt][1] = to_tf32(f1);
                a[mt][2] = to_tf32(f2);
                a[mt][3] = to_tf32(f3);
            }

#pragma unroll
            for (int mt = 0; mt < 4; mt++)
#pragma unroll
                for (int nt = 0; nt < 8; nt++) {
                    const uint32_t* qr = bq[nt >> 1];
                    uint32_t b0 = (nt & 1) ? qr[2] : qr[0];
                    uint32_t b1 = (nt & 1) ? qr[3] : qr[1];
                    asm volatile(
                        "mma.sync.aligned.m16n8k8.row.col.f32.tf32.tf32.f32 "
                        "{%0,%1,%2,%3}, {%4,%5,%6,%7}, {%8,%9}, {%0,%1,%2,%3};"
                        : "+f"(acc[mt][nt][0]), "+f"(acc[mt][nt][1]),
                          "+f"(acc[mt][nt][2]), "+f"(acc[mt][nt][3])
                        : "r"(a[mt][0]), "r"(a[mt][1]), "r"(a[mt][2]), "r"(a[mt][3]),
                          "r"(b0), "r"(b1));
                }
        }
    }

    // ---- epilogue: bias + relu + float2 stores ----
#pragma unroll
    for (int mt = 0; mt < 4; mt++) {
        int pix = mb * 128 + wm * 64 + mt * 16 + (l >> 2);
        float* o = out + ((size_t)b * 4096 + pix) * FOUT;
#pragma unroll
        for (int nt = 0; nt < 8; nt++) {
            int f0 = wn * 64 + nt * 8 + (l & 3) * 2;
            float m0v = sMB[f0], m1v = sMB[f0 + 1];
            float2 r0, r1;
            r0.x = fmaxf(acc[mt][nt][0] + m0v, 0.f);
            r0.y = fmaxf(acc[mt][nt][1] + m1v, 0.f);
            r1.x = fmaxf(acc[mt][nt][2] + m0v, 0.f);
            r1.y = fmaxf(acc[mt][nt][3] + m1v, 0.f);
            *(float2*)(o + f0) = r0;
            *(float2*)(o + (size_t)8 * FOUT + f0) = r1;
        }
    }
}

// ============================================================================
// kernel_launch — size-match (elements or bytes) + positional fallback.
// ============================================================================
extern "C" void kernel_launch(void* const* d_in, const int* in_sizes, int n_in,
                              void* d_out, int out_size) {
    const long long EX = 33554432LL, EW = 294912LL, EBI = 256LL,
                    EWE = 9437184LL, EBE = 8192LL;

    auto pick = [&](long long elems) -> const float* {
        for (int i = 0; i < n_in; i++) {
            long long s = (long long)in_sizes[i];
            if (s == elems || s == elems * 4) return (const float*)d_in[i];
        }
        return nullptr;
    };
    const float* X    = pick(EX);
    const float* W    = pick(EW);
    const float* bias = pick(EBI);
    const float* Werr = pick(EWE);
    const float* Berr = pick(EBE);

    if (!X || !W || !bias || !Werr || !Berr) {
        if (n_in >= 5) {
            X    = (const float*)d_in[0];
            W    = (const float*)d_in[1];
            bias = (const float*)d_in[2];
            Werr = (const float*)d_in[3];
            Berr = (const float*)d_in[4];
        } else {
            return;
        }
    }

    float* out = (float*)d_out;

    cudaFuncSetAttribute(conv_main, cudaFuncAttributeMaxDynamicSharedMemorySize,
                         (int)SMEM_TOTAL);

    prep_wfrag<<<BATCH * 9, 256>>>(W, Werr);
    conv_main<<<BATCH * 32, 256, SMEM_TOTAL>>>(X, bias, Berr, out);
}

// round 5
// speedup vs baseline: 2.1356x; 2.1356x over previous
#include <cuda_runtime.h>
#include <cuda_fp16.h>
#include <cstdint>

// ============================================================================
// ConvAConnect: per-sample perturbed 3x3 SAME conv, B=32 H=W=64 Cin=128 F=256
// R5: fp16 mma.sync.m16n8k16 (same 10-bit mantissa as tf32 -> same accuracy),
// B kept in registers straight from L2 (fragment-ordered fp16 table),
// A f32 through 2-stage cp.async smem pipeline, f32 accumulate.
// ============================================================================
static constexpr int BATCH = 32;
static constexpr int CIN   = 128;
static constexpr int FOUT  = 256;
static constexpr int NG16  = 72;    // K=1152 / 16
static constexpr int NCHUNK = 36;   // K / 32 (one A smem tile = 32 channels)

// fp16 per-sample weights in exact m16n8k16 B-fragment order:
// half index = ((b*72 + g)*4 + wn)*1024 + q*256 + lane*8 + e*4 + r*2 + p
//   wn=f>>6, q=(f>>4)&3, e=(f>>3)&1, lane=(f&7)*4 + ((c16&7)>>1),
//   r=c16>>3, p=c16&1.   Per (g,wn,q): 512B contiguous = warp LDG.128.
__device__ __align__(256) __half g_wfrag[(size_t)BATCH * NG16 * 4096];

__device__ __forceinline__ uint32_t smem_u32(const void* p) {
    uint32_t a;
    asm("{ .reg .u64 t; cvta.to.shared.u64 t, %1; cvt.u32.u64 %0, t; }" : "=r"(a) : "l"(p));
    return a;
}

// ============================================================================
// Prep: g_wfrag = frag_order(f16(W * Werr[b])). One block per (b, pos).
// 8 slabs of 16 channels; 8KB smem staging for coalesced writes.
// ============================================================================
__global__ void __launch_bounds__(256) prep_wfrag(const float* __restrict__ W,
                                                  const float* __restrict__ Werr) {
    __shared__ float4 st4[512];                    // 8KB = 4096 halves = one g16 slab
    __half* st = (__half*)st4;
    int blk = blockIdx.x;
    int b = blk / 9, pos = blk % 9;
    int f = threadIdx.x;                           // 0..255
    const float* wb = W    + (size_t)pos * CIN * FOUT + f;
    const float* eb = Werr + (size_t)(b * 9 + pos) * CIN * FOUT + f;
    const int wn = f >> 6, q = (f >> 4) & 3, e = (f >> 3) & 1;
    const int lane_base = (f & 7) * 4;

    for (int slab = 0; slab < 8; slab++) {         // 16 channels each
        __syncthreads();
#pragma unroll
        for (int ci = 0; ci < 16; ci++) {
            int c = slab * 16 + ci;
            float v = wb[(size_t)c * FOUT] * eb[(size_t)c * FOUT];
            int lane = lane_base + ((ci & 7) >> 1);
            int r = ci >> 3, p = ci & 1;
            st[wn * 1024 + q * 256 + lane * 8 + e * 4 + r * 2 + p] = __float2half_rn(v);
        }
        __syncthreads();
        int g = pos * 8 + slab;
        float4* dst = (float4*)(g_wfrag + (size_t)(b * NG16 + g) * 4096);
        dst[f * 2]     = st4[f * 2];
        dst[f * 2 + 1] = st4[f * 2 + 1];
    }
}

// ============================================================================
// Main: 1024 CTAs = 32 samples x 32 M-blocks (128 pixels = 2 image rows).
// 256 thr, 8 warps: wm=wid&1 (M half), wn=wid>>1 (N quarter); warp 64x64.
// A: f32, 2-stage cp.async, swizzle ^((row&3)<<5) -> conflict-free LDS.64.
// B: fp16 fragment table, register double-buffer, one-k16 prefetch.
// ============================================================================
__global__ void __launch_bounds__(256, 1)
conv_main(const float* __restrict__ X, const float* __restrict__ bias,
          const float* __restrict__ Berr, float* __restrict__ out) {
    __shared__ float4 sAbuf[2048];   // 32KB: 2 stages x (128 rows x 128B)
    __shared__ float sMB[256];
    const uint32_t sA = smem_u32(sAbuf);

    const int t = threadIdx.x, l = t & 31, wid = t >> 5;
    const int b = blockIdx.x >> 5, mb = blockIdx.x & 31;
    const int wm = wid & 1, wn = wid >> 1;

    sMB[t] = bias[t] * Berr[b * FOUT + t];

    // ---- A producer: thread t covers row t/2, 4 x 16B segs ----
    const int arow = t >> 1;
    const uint32_t aseg0 = (uint32_t)((t & 1) * 4);
    const uint32_t asw = (uint32_t)((arow & 3) << 5);

    auto issueA = [&](int s, int stage) {
        int pos = s >> 2, cb = s & 3;
        int kh = pos / 3, kw = pos % 3;
        int y = mb * 2 + (arow >> 6) + kh - 1;
        int x = (arow & 63) + kw - 1;
        bool valid = ((unsigned)y < 64u) && ((unsigned)x < 64u);
        const float* src = X + (((size_t)b * 64 + (valid ? y : 0)) * 64 +
                                (valid ? x : 0)) * CIN + cb * 32;
        int sz = valid ? 16 : 0;
        uint32_t dbase = sA + (uint32_t)stage * 16384u + (uint32_t)arow * 128u;
#pragma unroll
        for (int jj = 0; jj < 4; jj++) {
            uint32_t seg = aseg0 + (uint32_t)jj;
            uint32_t d = dbase + ((seg * 16u) ^ asw);
            asm volatile("cp.async.cg.shared.global [%0], [%1], 16, %2;"
                         :: "r"(d), "l"(src + seg * 4), "r"(sz) : "memory");
        }
        asm volatile("cp.async.commit_group;" ::: "memory");
    };

    // ---- B fragment base pointer (uint4 units: 8 halves each) ----
    const uint4* bp = (const uint4*)g_wfrag +
                      (size_t)b * NG16 * 512 + wn * 128 + l;

    float acc[4][8][4];
#pragma unroll
    for (int mt = 0; mt < 4; mt++)
#pragma unroll
        for (int nt = 0; nt < 8; nt++)
#pragma unroll
            for (int qq = 0; qq < 4; qq++) acc[mt][nt][qq] = 0.f;

    // Prologue
    issueA(0, 0);
    uint4 bf[2][4];
#pragma unroll
    for (int qq = 0; qq < 4; qq++) bf[0][qq] = bp[qq * 32];   // g = 0

    const int tig = l & 3;                 // thread-in-group (k quad)
    const uint32_t tof = (uint32_t)(tig * 8);

    for (int s = 0; s < NCHUNK; s++) {
        asm volatile("cp.async.wait_group 0;" ::: "memory");
        __syncthreads();
        if (s + 1 < NCHUNK) issueA(s + 1, (s + 1) & 1);
        const uint32_t stb = sA + (uint32_t)(s & 1) * 16384u;

#pragma unroll
        for (int kk = 0; kk < 2; kk++) {          // two k16 per 32-channel tile
            int g = s * 2 + kk;
            int gn = (g + 1 < NG16 * 1) ? g + 1 : g;
            // prefetch next k16 B fragments
            uint4* nb = bf[(kk + 1) & 1];
#pragma unroll
            for (int qq = 0; qq < 4; qq++) nb[qq] = bp[(size_t)gn * 512 + qq * 32];

            // A fragments: LDS.64 f32 pairs -> cvt.rn.f16x2
            uint32_t a[4][4];
            const uint32_t kb = (uint32_t)(kk * 64) + tof;
#pragma unroll
            for (int mt = 0; mt < 4; mt++) {
                int r0 = wm * 64 + mt * 16 + (l >> 2);
                uint32_t b0r = stb + (uint32_t)r0 * 128u;
                uint32_t b1r = b0r + 8u * 128u;
                uint32_t sw0 = (uint32_t)((r0 & 3) << 5);
                uint32_t sw1 = (uint32_t)(((r0 + 8) & 3) << 5);
                float f0, f1, f2, f3, f4, f5, f6, f7;
                asm volatile("ld.shared.v2.f32 {%0,%1}, [%2];"
                             : "=f"(f0), "=f"(f1) : "r"(b0r + (kb ^ sw0)));
                asm volatile("ld.shared.v2.f32 {%0,%1}, [%2];"
                             : "=f"(f2), "=f"(f3) : "r"(b1r + (kb ^ sw1)));
                asm volatile("ld.shared.v2.f32 {%0,%1}, [%2];"
                             : "=f"(f4), "=f"(f5) : "r"(b0r + ((kb + 32u) ^ sw0)));
                asm volatile("ld.shared.v2.f32 {%0,%1}, [%2];"
                             : "=f"(f6), "=f"(f7) : "r"(b1r + ((kb + 32u) ^ sw1)));
                // pack: low half = first channel
                asm volatile("cvt.rn.f16x2.f32 %0, %1, %2;" : "=r"(a[mt][0]) : "f"(f1), "f"(f0));
                asm volatile("cvt.rn.f16x2.f32 %0, %1, %2;" : "=r"(a[mt][1]) : "f"(f3), "f"(f2));
                asm volatile("cvt.rn.f16x2.f32 %0, %1, %2;" : "=r"(a[mt][2]) : "f"(f5), "f"(f4));
                asm volatile("cvt.rn.f16x2.f32 %0, %1, %2;" : "=r"(a[mt][3]) : "f"(f7), "f"(f6));
            }

            const uint4* cb = bf[kk & 1];
#pragma unroll
            for (int mt = 0; mt < 4; mt++)
#pragma unroll
                for (int nt = 0; nt < 8; nt++) {
                    const uint4 qv = cb[nt >> 1];
                    uint32_t b0, b1;
                    if (nt & 1) { b0 = qv.z; b1 = qv.w; }
                    else        { b0 = qv.x; b1 = qv.y; }
                    asm volatile(
                        "mma.sync.aligned.m16n8k16.row.col.f32.f16.f16.f32 "
                        "{%0,%1,%2,%3}, {%4,%5,%6,%7}, {%8,%9}, {%0,%1,%2,%3};"
                        : "+f"(acc[mt][nt][0]), "+f"(acc[mt][nt][1]),
                          "+f"(acc[mt][nt][2]), "+f"(acc[mt][nt][3])
                        : "r"(a[mt][0]), "r"(a[mt][1]), "r"(a[mt][2]), "r"(a[mt][3]),
                          "r"(b0), "r"(b1));
                }
        }
    }

    // ---- epilogue: bias + relu + float2 stores ----
#pragma unroll
    for (int mt = 0; mt < 4; mt++) {
        int pix = mb * 128 + wm * 64 + mt * 16 + (l >> 2);
        float* o = out + ((size_t)b * 4096 + pix) * FOUT;
#pragma unroll
        for (int nt = 0; nt < 8; nt++) {
            int f0 = wn * 64 + nt * 8 + (l & 3) * 2;
            float m0v = sMB[f0], m1v = sMB[f0 + 1];
            float2 r0, r1;
            r0.x = fmaxf(acc[mt][nt][0] + m0v, 0.f);
            r0.y = fmaxf(acc[mt][nt][1] + m1v, 0.f);
            r1.x = fmaxf(acc[mt][nt][2] + m0v, 0.f);
            r1.y = fmaxf(acc[mt][nt][3] + m1v, 0.f);
            *(float2*)(o + f0) = r0;
            *(float2*)(o + (size_t)8 * FOUT + f0) = r1;
        }
    }
}

// ============================================================================
// kernel_launch — size-match (elements or bytes) + positional fallback.
// ============================================================================
extern "C" void kernel_launch(void* const* d_in, const int* in_sizes, int n_in,
                              void* d_out, int out_size) {
    const long long EX = 33554432LL, EW = 294912LL, EBI = 256LL,
                    EWE = 9437184LL, EBE = 8192LL;

    auto pick = [&](long long elems) -> const float* {
        for (int i = 0; i < n_in; i++) {
            long long s = (long long)in_sizes[i];
            if (s == elems || s == elems * 4) return (const float*)d_in[i];
        }
        return nullptr;
    };
    const float* X    = pick(EX);
    const float* W    = pick(EW);
    const float* bias = pick(EBI);
    const float* Werr = pick(EWE);
    const float* Berr = pick(EBE);

    if (!X || !W || !bias || !Werr || !Berr) {
        if (n_in >= 5) {
            X    = (const float*)d_in[0];
            W    = (const float*)d_in[1];
            bias = (const float*)d_in[2];
            Werr = (const float*)d_in[3];
            Berr = (const float*)d_in[4];
        } else {
            return;
        }
    }

    float* out = (float*)d_out;

    prep_wfrag<<<BATCH * 9, 256>>>(W, Werr);
    conv_main<<<BATCH * 32, 256>>>(X, bias, Berr, out);
}

// round 7
// speedup vs baseline: 2.2653x; 1.0608x over previous
#include <cuda_runtime.h>
#include <cuda_fp16.h>
#include <cstdint>

// ============================================================================
// ConvAConnect: per-sample perturbed 3x3 SAME conv, B=32 H=W=64 Cin=128 F=256
// R7: R6 design (fp16 m16n8k16, 512-thread CTAs, warp tile 32x64, 3-stage
// cp.async A pipeline, B register-prefetched from L2) with the A-producer
// bug fixed: each thread now copies TWO 16B segments (full 128B rows).
// ============================================================================
static constexpr int BATCH = 32;
static constexpr int CIN   = 128;
static constexpr int FOUT  = 256;
static constexpr int NG16  = 72;    // K=1152 / 16
static constexpr int NCHUNK = 36;   // K / 32 (one A smem tile = 32 channels)
static constexpr int NSTAGE = 3;

// fp16 per-sample weights in exact m16n8k16 B-fragment order:
// half index = ((b*72 + g)*4 + wn)*1024 + q*256 + lane*8 + e*4 + r*2 + p
//   wn=f>>6, q=(f>>4)&3, e=(f>>3)&1, lane=(f&7)*4 + ((c16&7)>>1),
//   r=c16>>3, p=c16&1.   Per (g,wn,q): 512B contiguous = warp LDG.128.
__device__ __align__(256) __half g_wfrag[(size_t)BATCH * NG16 * 4096];

__device__ __forceinline__ uint32_t smem_u32(const void* p) {
    uint32_t a;
    asm("{ .reg .u64 t; cvta.to.shared.u64 t, %1; cvt.u32.u64 %0, t; }" : "=r"(a) : "l"(p));
    return a;
}

// ============================================================================
// Prep: g_wfrag = frag_order(f16(W * Werr[b])). One block per (b, pos).
// ============================================================================
__global__ void __launch_bounds__(256) prep_wfrag(const float* __restrict__ W,
                                                  const float* __restrict__ Werr) {
    __shared__ float4 st4[512];                    // 8KB = 4096 halves
    __half* st = (__half*)st4;
    int blk = blockIdx.x;
    int b = blk / 9, pos = blk % 9;
    int f = threadIdx.x;                           // 0..255
    const float* wb = W    + (size_t)pos * CIN * FOUT + f;
    const float* eb = Werr + (size_t)(b * 9 + pos) * CIN * FOUT + f;
    const int wn = f >> 6, q = (f >> 4) & 3, e = (f >> 3) & 1;
    const int lane_base = (f & 7) * 4;

    for (int slab = 0; slab < 8; slab++) {         // 16 channels each
        __syncthreads();
#pragma unroll
        for (int ci = 0; ci < 16; ci++) {
            int c = slab * 16 + ci;
            float v = wb[(size_t)c * FOUT] * eb[(size_t)c * FOUT];
            int lane = lane_base + ((ci & 7) >> 1);
            int r = ci >> 3, p = ci & 1;
            st[wn * 1024 + q * 256 + lane * 8 + e * 4 + r * 2 + p] = __float2half_rn(v);
        }
        __syncthreads();
        int g = pos * 8 + slab;
        float4* dst = (float4*)(g_wfrag + (size_t)(b * NG16 + g) * 4096);
        dst[f * 2]     = st4[f * 2];
        dst[f * 2 + 1] = st4[f * 2 + 1];
    }
}

// ============================================================================
// Main: 1024 CTAs = 32 samples x 32 M-blocks (128 pixels). 512 threads.
// 16 warps: wm = wid&3 (32-row M quarter), wn = wid>>2 (64-col N quarter).
// ============================================================================
__global__ void __launch_bounds__(512, 1)
conv_main(const float* __restrict__ X, const float* __restrict__ bias,
          const float* __restrict__ Berr, float* __restrict__ out) {
    __shared__ float4 sAbuf[NSTAGE * 1024];   // 3 stages x 16KB
    __shared__ float sMB[256];
    const uint32_t sA = smem_u32(sAbuf);

    const int t = threadIdx.x, l = t & 31, wid = t >> 5;
    const int b = blockIdx.x >> 5, mb = blockIdx.x & 31;
    const int wm = wid & 3, wn = wid >> 2;

    if (t < 256) sMB[t] = bias[t] * Berr[b * FOUT + t];

    // ---- A producer: thread t covers row t>>2, segs (t&3) and (t&3)+4 ----
    const int arow = t >> 2;
    const uint32_t aseg = (uint32_t)(t & 3);
    const uint32_t asw = (uint32_t)((arow & 3) << 5);

    auto issueA = [&](int s) {
        int stage = s % NSTAGE;
        int pos = s >> 2, cb = s & 3;
        int kh = pos / 3, kw = pos % 3;
        int y = mb * 2 + (arow >> 6) + kh - 1;
        int x = (arow & 63) + kw - 1;
        bool valid = ((unsigned)y < 64u) && ((unsigned)x < 64u);
        const float* src = X + (((size_t)b * 64 + (valid ? y : 0)) * 64 +
                                (valid ? x : 0)) * CIN + cb * 32;
        int sz = valid ? 16 : 0;
        uint32_t dbase = sA + (uint32_t)stage * 16384u + (uint32_t)arow * 128u;
        uint32_t d0 = dbase + ((aseg * 16u) ^ asw);
        uint32_t d1 = dbase + (((aseg + 4u) * 16u) ^ asw);
        asm volatile("cp.async.cg.shared.global [%0], [%1], 16, %2;"
                     :: "r"(d0), "l"(src + aseg * 4), "r"(sz) : "memory");
        asm volatile("cp.async.cg.shared.global [%0], [%1], 16, %2;"
                     :: "r"(d1), "l"(src + (aseg + 4u) * 4), "r"(sz) : "memory");
        asm volatile("cp.async.commit_group;" ::: "memory");
    };

    // ---- B fragment base pointer (uint4 units: 8 halves each) ----
    const uint4* bp = (const uint4*)g_wfrag +
                      (size_t)b * NG16 * 512 + wn * 128 + l;

    float acc[2][8][4];
#pragma unroll
    for (int mt = 0; mt < 2; mt++)
#pragma unroll
        for (int nt = 0; nt < 8; nt++)
#pragma unroll
            for (int qq = 0; qq < 4; qq++) acc[mt][nt][qq] = 0.f;

    // Prologue: 2 stages in flight, first B fragment set in regs
    issueA(0);
    issueA(1);
    uint4 bf[2][4];
#pragma unroll
    for (int qq = 0; qq < 4; qq++) bf[0][qq] = bp[qq * 32];   // g = 0

    const uint32_t tof = (uint32_t)((l & 3) * 8);

    for (int s = 0; s < NCHUNK; s++) {
        if (s + 1 < NCHUNK)
            asm volatile("cp.async.wait_group 1;" ::: "memory");
        else
            asm volatile("cp.async.wait_group 0;" ::: "memory");
        __syncthreads();
        if (s + 2 < NCHUNK) issueA(s + 2);

        const uint32_t stb = sA + (uint32_t)(s % NSTAGE) * 16384u;

#pragma unroll
        for (int kk = 0; kk < 2; kk++) {          // two k16 per 32-channel tile
            int g = s * 2 + kk;
            int gn = (g + 1 < NG16) ? g + 1 : g;
            // prefetch next k16 B fragments
            uint4* nb = bf[(kk + 1) & 1];
#pragma unroll
            for (int qq = 0; qq < 4; qq++) nb[qq] = bp[(size_t)gn * 512 + qq * 32];

            // A fragments: LDS.64 f32 pairs -> cvt.rn.f16x2
            uint32_t a[2][4];
            const uint32_t kb = (uint32_t)(kk * 64) + tof;
#pragma unroll
            for (int mt = 0; mt < 2; mt++) {
                int r0 = wm * 32 + mt * 16 + (l >> 2);
                uint32_t b0r = stb + (uint32_t)r0 * 128u;
                uint32_t b1r = b0r + 8u * 128u;
                uint32_t sw0 = (uint32_t)((r0 & 3) << 5);
                uint32_t sw1 = (uint32_t)(((r0 + 8) & 3) << 5);
                float f0, f1, f2, f3, f4, f5, f6, f7;
                asm volatile("ld.shared.v2.f32 {%0,%1}, [%2];"
                             : "=f"(f0), "=f"(f1) : "r"(b0r + (kb ^ sw0)));
                asm volatile("ld.shared.v2.f32 {%0,%1}, [%2];"
                             : "=f"(f2), "=f"(f3) : "r"(b1r + (kb ^ sw1)));
                asm volatile("ld.shared.v2.f32 {%0,%1}, [%2];"
                             : "=f"(f4), "=f"(f5) : "r"(b0r + ((kb + 32u) ^ sw0)));
                asm volatile("ld.shared.v2.f32 {%0,%1}, [%2];"
                             : "=f"(f6), "=f"(f7) : "r"(b1r + ((kb + 32u) ^ sw1)));
                asm volatile("cvt.rn.f16x2.f32 %0, %1, %2;" : "=r"(a[mt][0]) : "f"(f1), "f"(f0));
                asm volatile("cvt.rn.f16x2.f32 %0, %1, %2;" : "=r"(a[mt][1]) : "f"(f3), "f"(f2));
                asm volatile("cvt.rn.f16x2.f32 %0, %1, %2;" : "=r"(a[mt][2]) : "f"(f5), "f"(f4));
                asm volatile("cvt.rn.f16x2.f32 %0, %1, %2;" : "=r"(a[mt][3]) : "f"(f7), "f"(f6));
            }

            const uint4* cb = bf[kk & 1];
#pragma unroll
            for (int mt = 0; mt < 2; mt++)
#pragma unroll
                for (int nt = 0; nt < 8; nt++) {
                    const uint4 qv = cb[nt >> 1];
                    uint32_t b0, b1;
                    if (nt & 1) { b0 = qv.z; b1 = qv.w; }
                    else        { b0 = qv.x; b1 = qv.y; }
                    asm volatile(
                        "mma.sync.aligned.m16n8k16.row.col.f32.f16.f16.f32 "
                        "{%0,%1,%2,%3}, {%4,%5,%6,%7}, {%8,%9}, {%0,%1,%2,%3};"
                        : "+f"(acc[mt][nt][0]), "+f"(acc[mt][nt][1]),
                          "+f"(acc[mt][nt][2]), "+f"(acc[mt][nt][3])
                        : "r"(a[mt][0]), "r"(a[mt][1]), "r"(a[mt][2]), "r"(a[mt][3]),
                          "r"(b0), "r"(b1));
                }
        }
    }

    // ---- epilogue: bias + relu + float2 stores ----
#pragma unroll
    for (int mt = 0; mt < 2; mt++) {
        int pix = mb * 128 + wm * 32 + mt * 16 + (l >> 2);
        float* o = out + ((size_t)b * 4096 + pix) * FOUT;
#pragma unroll
        for (int nt = 0; nt < 8; nt++) {
            int f0 = wn * 64 + nt * 8 + (l & 3) * 2;
            float m0v = sMB[f0], m1v = sMB[f0 + 1];
            float2 r0, r1;
            r0.x = fmaxf(acc[mt][nt][0] + m0v, 0.f);
            r0.y = fmaxf(acc[mt][nt][1] + m1v, 0.f);
            r1.x = fmaxf(acc[mt][nt][2] + m0v, 0.f);
            r1.y = fmaxf(acc[mt][nt][3] + m1v, 0.f);
            *(float2*)(o + f0) = r0;
            *(float2*)(o + (size_t)8 * FOUT + f0) = r1;
        }
    }
}

// ============================================================================
// kernel_launch — size-match (elements or bytes) + positional fallback.
// ============================================================================
extern "C" void kernel_launch(void* const* d_in, const int* in_sizes, int n_in,
                              void* d_out, int out_size) {
    const long long EX = 33554432LL, EW = 294912LL, EBI = 256LL,
                    EWE = 9437184LL, EBE = 8192LL;

    auto pick = [&](long long elems) -> const float* {
        for (int i = 0; i < n_in; i++) {
            long long s = (long long)in_sizes[i];
            if (s == elems || s == elems * 4) return (const float*)d_in[i];
        }
        return nullptr;
    };
    const float* X    = pick(EX);
    const float* W    = pick(EW);
    const float* bias = pick(EBI);
    const float* Werr = pick(EWE);
    const float* Berr = pick(EBE);

    if (!X || !W || !bias || !Werr || !Berr) {
        if (n_in >= 5) {
            X    = (const float*)d_in[0];
            W    = (const float*)d_in[1];
            bias = (const float*)d_in[2];
            Werr = (const float*)d_in[3];
            Berr = (const float*)d_in[4];
        } else {
            return;
        }
    }

    float* out = (float*)d_out;

    prep_wfrag<<<BATCH * 9, 256>>>(W, Werr);
    conv_main<<<BATCH * 32, 512>>>(X, bias, Berr, out);
}

// round 8
// speedup vs baseline: 2.3269x; 1.0272x over previous
#include <cuda_runtime.h>
#include <cuda_fp16.h>
#include <cstdint>

// ============================================================================
// ConvAConnect: per-sample perturbed 3x3 SAME conv, B=32 H=W=64 Cin=128 F=256
// R8: fp16 A tiles in smem (producer LDG f32 -> cvt -> STS fp16, register
// software pipeline), consumed via ldmatrix.x4. 64-channel stages (18 iters).
// B: fp16 fragment table in L2, register prefetch. fp16 m16n8k16, f32 accum.
// ============================================================================
static constexpr int BATCH = 32;
static constexpr int CIN   = 128;
static constexpr int FOUT  = 256;
static constexpr int NG16  = 72;    // K=1152 / 16
static constexpr int NST   = 18;    // stages: 64 channels each
static constexpr uint32_t ABUF = 16384;  // 128 rows x 128B fp16 per stage

// fp16 per-sample weights in exact m16n8k16 B-fragment order (same as R5/R7):
// half index = ((b*72 + g)*4 + wn)*1024 + q*256 + lane*8 + e*4 + r*2 + p
__device__ __align__(256) __half g_wfrag[(size_t)BATCH * NG16 * 4096];

__device__ __forceinline__ uint32_t smem_u32(const void* p) {
    uint32_t a;
    asm("{ .reg .u64 t; cvta.to.shared.u64 t, %1; cvt.u32.u64 %0, t; }" : "=r"(a) : "l"(p));
    return a;
}

// ============================================================================
// Prep: g_wfrag = frag_order(f16(W * Werr[b])). One block per (b, pos).
// ============================================================================
__global__ void __launch_bounds__(256) prep_wfrag(const float* __restrict__ W,
                                                  const float* __restrict__ Werr) {
    __shared__ float4 st4[512];                    // 8KB = 4096 halves
    __half* st = (__half*)st4;
    int blk = blockIdx.x;
    int b = blk / 9, pos = blk % 9;
    int f = threadIdx.x;                           // 0..255
    const float* wb = W    + (size_t)pos * CIN * FOUT + f;
    const float* eb = Werr + (size_t)(b * 9 + pos) * CIN * FOUT + f;
    const int wn = f >> 6, q = (f >> 4) & 3, e = (f >> 3) & 1;
    const int lane_base = (f & 7) * 4;

    for (int slab = 0; slab < 8; slab++) {         // 16 channels each
        __syncthreads();
#pragma unroll
        for (int ci = 0; ci < 16; ci++) {
            int c = slab * 16 + ci;
            float v = wb[(size_t)c * FOUT] * eb[(size_t)c * FOUT];
            int lane = lane_base + ((ci & 7) >> 1);
            int r = ci >> 3, p = ci & 1;
            st[wn * 1024 + q * 256 + lane * 8 + e * 4 + r * 2 + p] = __float2half_rn(v);
        }
        __syncthreads();
        int g = pos * 8 + slab;
        float4* dst = (float4*)(g_wfrag + (size_t)(b * NG16 + g) * 4096);
        dst[f * 2]     = st4[f * 2];
        dst[f * 2 + 1] = st4[f * 2 + 1];
    }
}

// ============================================================================
// Main: 1024 CTAs = 32 samples x 32 M-blocks (128 pixels). 512 threads.
// 16 warps: wm = wid&3 (32-row M quarter), wn = wid>>2 (64-col N quarter).
// ============================================================================
__global__ void __launch_bounds__(512, 1)
conv_main(const float* __restrict__ X, const float* __restrict__ bias,
          const float* __restrict__ Berr, float* __restrict__ out) {
    __shared__ float4 sAbuf[2048];   // 32KB: 2 stages x 16KB fp16
    __shared__ float sMB[256];
    const uint32_t sA = smem_u32(sAbuf);

    const int t = threadIdx.x, l = t & 31, wid = t >> 5;
    const int b = blockIdx.x >> 5, mb = blockIdx.x & 31;
    const int wm = wid & 3, wn = wid >> 2;

    if (t < 256) sMB[t] = bias[t] * Berr[b * FOUT + t];

    // ---- A producer: thread t -> row t>>2, channel quarter q = t&3 ----
    const int row = t >> 2, q = t & 3;
    const int rs7 = row & 7;
    float4 xf[4];                               // 16 f32 channels held

    auto loadX = [&](int s) {
        int pos = s >> 1;                       // 0..8
        int c0 = (s & 1) * 64 + q * 16;
        int kh = pos / 3, kw = pos % 3;
        int y = mb * 2 + (row >> 6) + kh - 1;
        int x = (row & 63) + kw - 1;
        bool valid = ((unsigned)y < 64u) && ((unsigned)x < 64u);
        const float4* src = (const float4*)(X +
            (((size_t)b * 64 + (valid ? y : 0)) * 64 + (valid ? x : 0)) * CIN + c0);
        if (valid) {
            xf[0] = src[0]; xf[1] = src[1]; xf[2] = src[2]; xf[3] = src[3];
        } else {
            float4 z = make_float4(0.f, 0.f, 0.f, 0.f);
            xf[0] = z; xf[1] = z; xf[2] = z; xf[3] = z;
        }
    };
    auto stsX = [&](int buf) {
        uint32_t h[8];
        asm volatile("cvt.rn.f16x2.f32 %0, %1, %2;" : "=r"(h[0]) : "f"(xf[0].y), "f"(xf[0].x));
        asm volatile("cvt.rn.f16x2.f32 %0, %1, %2;" : "=r"(h[1]) : "f"(xf[0].w), "f"(xf[0].z));
        asm volatile("cvt.rn.f16x2.f32 %0, %1, %2;" : "=r"(h[2]) : "f"(xf[1].y), "f"(xf[1].x));
        asm volatile("cvt.rn.f16x2.f32 %0, %1, %2;" : "=r"(h[3]) : "f"(xf[1].w), "f"(xf[1].z));
        asm volatile("cvt.rn.f16x2.f32 %0, %1, %2;" : "=r"(h[4]) : "f"(xf[2].y), "f"(xf[2].x));
        asm volatile("cvt.rn.f16x2.f32 %0, %1, %2;" : "=r"(h[5]) : "f"(xf[2].w), "f"(xf[2].z));
        asm volatile("cvt.rn.f16x2.f32 %0, %1, %2;" : "=r"(h[6]) : "f"(xf[3].y), "f"(xf[3].x));
        asm volatile("cvt.rn.f16x2.f32 %0, %1, %2;" : "=r"(h[7]) : "f"(xf[3].w), "f"(xf[3].z));
        uint32_t base = sA + (uint32_t)buf * ABUF + (uint32_t)row * 128u;
        uint32_t d0 = base + (uint32_t)(((q * 2)     ^ rs7) * 16);
        uint32_t d1 = base + (uint32_t)(((q * 2 + 1) ^ rs7) * 16);
        asm volatile("st.shared.v4.b32 [%0], {%1,%2,%3,%4};"
                     :: "r"(d0), "r"(h[0]), "r"(h[1]), "r"(h[2]), "r"(h[3]) : "memory");
        asm volatile("st.shared.v4.b32 [%0], {%1,%2,%3,%4};"
                     :: "r"(d1), "r"(h[4]), "r"(h[5]), "r"(h[6]), "r"(h[7]) : "memory");
    };

    // ---- consumer ldmatrix lane addressing (per mt, seg varies with kk) ----
    const int lm = l >> 3, lri = l & 7;
    const int rowA0 = wm * 32 + lri + (lm & 1) * 8;   // + mt*16
    const uint32_t segHi = (uint32_t)(lm >> 1);       // 0: k0-7, 1: k8-15

    // ---- B fragment base pointer (uint4 units: 8 halves each) ----
    const uint4* bp = (const uint4*)g_wfrag +
                      (size_t)b * NG16 * 512 + wn * 128 + l;

    float acc[2][8][4];
#pragma unroll
    for (int mt = 0; mt < 2; mt++)
#pragma unroll
        for (int nt = 0; nt < 8; nt++)
#pragma unroll
            for (int qq = 0; qq < 4; qq++) acc[mt][nt][qq] = 0.f;

    // Prologue: stage 0 into buf0, stage 1 held in regs, B g=0 in regs
    loadX(0);
    stsX(0);
    loadX(1);
    uint4 bf[2][4];
#pragma unroll
    for (int qq = 0; qq < 4; qq++) bf[0][qq] = bp[qq * 32];
    __syncthreads();

    for (int s = 0; s < NST; s++) {
        if (s + 1 < NST) stsX((s + 1) & 1);
        if (s + 2 < NST) loadX(s + 2);

        const uint32_t abuf = sA + (uint32_t)(s & 1) * ABUF;

#pragma unroll
        for (int kk = 0; kk < 4; kk++) {          // four k16 per 64-ch stage
            int g = s * 4 + kk;
            int gn = (g + 1 < NG16) ? g + 1 : g;
            uint4* nb = bf[(kk + 1) & 1];
#pragma unroll
            for (int qq = 0; qq < 4; qq++) nb[qq] = bp[(size_t)gn * 512 + qq * 32];

            // A fragments via ldmatrix.x4 (one per mt)
            uint32_t a[2][4];
            const uint32_t seg = (uint32_t)(kk * 2) + segHi;
#pragma unroll
            for (int mt = 0; mt < 2; mt++) {
                int rr = rowA0 + mt * 16;
                uint32_t addr = abuf + (uint32_t)rr * 128u +
                                ((seg ^ (uint32_t)(rr & 7)) * 16u);
                asm volatile("ldmatrix.sync.aligned.m8n8.x4.shared.b16 "
                             "{%0,%1,%2,%3}, [%4];"
                             : "=r"(a[mt][0]), "=r"(a[mt][1]),
                               "=r"(a[mt][2]), "=r"(a[mt][3])
                             : "r"(addr));
            }

            const uint4* cb = bf[kk & 1];
#pragma unroll
            for (int mt = 0; mt < 2; mt++)
#pragma unroll
                for (int nt = 0; nt < 8; nt++) {
                    const uint4 qv = cb[nt >> 1];
                    uint32_t b0, b1;
                    if (nt & 1) { b0 = qv.z; b1 = qv.w; }
                    else        { b0 = qv.x; b1 = qv.y; }
                    asm volatile(
                        "mma.sync.aligned.m16n8k16.row.col.f32.f16.f16.f32 "
                        "{%0,%1,%2,%3}, {%4,%5,%6,%7}, {%8,%9}, {%0,%1,%2,%3};"
                        : "+f"(acc[mt][nt][0]), "+f"(acc[mt][nt][1]),
                          "+f"(acc[mt][nt][2]), "+f"(acc[mt][nt][3])
                        : "r"(a[mt][0]), "r"(a[mt][1]), "r"(a[mt][2]), "r"(a[mt][3]),
                          "r"(b0), "r"(b1));
                }
        }
        __syncthreads();
    }

    // ---- epilogue: bias + relu + float2 stores ----
#pragma unroll
    for (int mt = 0; mt < 2; mt++) {
        int pix = mb * 128 + wm * 32 + mt * 16 + (l >> 2);
        float* o = out + ((size_t)b * 4096 + pix) * FOUT;
#pragma unroll
        for (int nt = 0; nt < 8; nt++) {
            int f0 = wn * 64 + nt * 8 + (l & 3) * 2;
            float m0v = sMB[f0], m1v = sMB[f0 + 1];
            float2 r0, r1;
            r0.x = fmaxf(acc[mt][nt][0] + m0v, 0.f);
            r0.y = fmaxf(acc[mt][nt][1] + m1v, 0.f);
            r1.x = fmaxf(acc[mt][nt][2] + m0v, 0.f);
            r1.y = fmaxf(acc[mt][nt][3] + m1v, 0.f);
            *(float2*)(o + f0) = r0;
            *(float2*)(o + (size_t)8 * FOUT + f0) = r1;
        }
    }
}

// ============================================================================
// kernel_launch — size-match (elements or bytes) + positional fallback.
// ============================================================================
extern "C" void kernel_launch(void* const* d_in, const int* in_sizes, int n_in,
                              void* d_out, int out_size) {
    const long long EX = 33554432LL, EW = 294912LL, EBI = 256LL,
                    EWE = 9437184LL, EBE = 8192LL;

    auto pick = [&](long long elems) -> const float* {
        for (int i = 0; i < n_in; i++) {
            long long s = (long long)in_sizes[i];
            if (s == elems || s == elems * 4) return (const float*)d_in[i];
        }
        return nullptr;
    };
    const float* X    = pick(EX);
    const float* W    = pick(EW);
    const float* bias = pick(EBI);
    const float* Werr = pick(EWE);
    const float* Berr = pick(EBE);

    if (!X || !W || !bias || !Werr || !Berr) {
        if (n_in >= 5) {
            X    = (const float*)d_in[0];
            W    = (const float*)d_in[1];
            bias = (const float*)d_in[2];
            Werr = (const float*)d_in[3];
            Berr = (const float*)d_in[4];
        } else {
            return;
        }
    }

    float* out = (float*)d_out;

    prep_wfrag<<<BATCH * 9, 256>>>(W, Werr);
    conv_main<<<BATCH * 32, 512>>>(X, bias, Berr, out);
}

// round 10
// speedup vs baseline: 2.4059x; 1.0339x over previous
#include <cuda_runtime.h>
#include <cuda_fp16.h>
#include <cstdint>

// ============================================================================
// ConvAConnect: per-sample perturbed 3x3 SAME conv, B=32 H=W=64 Cin=128 F=256
// R9: 128-channel stages (9 barriers), producer interleaved between k16
// bodies in quarters; fp16 A in smem via ldmatrix; B fp16 fragment table in
// L2 with register prefetch. fp16 m16n8k16, f32 accumulate.
// ============================================================================
static constexpr int BATCH = 32;
static constexpr int CIN   = 128;
static constexpr int FOUT  = 256;
static constexpr int NG16  = 72;    // K=1152 / 16
static constexpr int NPOS  = 9;     // stages: one conv position = 128 ch each
static constexpr uint32_t ABUF = 32768;            // 128 rows x 256B fp16
static constexpr uint32_t SMEM_TOTAL = 2 * ABUF + 1024;

// fp16 per-sample weights in exact m16n8k16 B-fragment order (same as R5-R8):
// half index = ((b*72 + g)*4 + wn)*1024 + q*256 + lane*8 + e*4 + r*2 + p
__device__ __align__(256) __half g_wfrag[(size_t)BATCH * NG16 * 4096];

__device__ __forceinline__ uint32_t smem_u32(const void* p) {
    uint32_t a;
    asm("{ .reg .u64 t; cvta.to.shared.u64 t, %1; cvt.u32.u64 %0, t; }" : "=r"(a) : "l"(p));
    return a;
}

// ============================================================================
// Prep: g_wfrag = frag_order(f16(W * Werr[b])). One block per (b, pos).
// ============================================================================
__global__ void __launch_bounds__(256) prep_wfrag(const float* __restrict__ W,
                                                  const float* __restrict__ Werr) {
    __shared__ float4 st4[512];                    // 8KB = 4096 halves
    __half* st = (__half*)st4;
    int blk = blockIdx.x;
    int b = blk / 9, pos = blk % 9;
    int f = threadIdx.x;                           // 0..255
    const float* wb = W    + (size_t)pos * CIN * FOUT + f;
    const float* eb = Werr + (size_t)(b * 9 + pos) * CIN * FOUT + f;
    const int wn = f >> 6, q = (f >> 4) & 3, e = (f >> 3) & 1;
    const int lane_base = (f & 7) * 4;

    for (int slab = 0; slab < 8; slab++) {         // 16 channels each
        __syncthreads();
#pragma unroll
        for (int ci = 0; ci < 16; ci++) {
            int c = slab * 16 + ci;
            float v = wb[(size_t)c * FOUT] * eb[(size_t)c * FOUT];
            int lane = lane_base + ((ci & 7) >> 1);
            int r = ci >> 3, p = ci & 1;
            st[wn * 1024 + q * 256 + lane * 8 + e * 4 + r * 2 + p] = __float2half_rn(v);
        }
        __syncthreads();
        int g = pos * 8 + slab;
        float4* dst = (float4*)(g_wfrag + (size_t)(b * NG16 + g) * 4096);
        dst[f * 2]     = st4[f * 2];
        dst[f * 2 + 1] = st4[f * 2 + 1];
    }
}

// ============================================================================
// Main: 1024 CTAs = 32 samples x 32 M-blocks (128 pixels). 512 threads.
// 16 warps: wm = wid&3 (32-row M quarter), wn = wid>>2 (64-col N quarter).
// ============================================================================
__global__ void __launch_bounds__(512, 1)
conv_main(const float* __restrict__ X, const float* __restrict__ bias,
          const float* __restrict__ Berr, float* __restrict__ out) {
    extern __shared__ char smem[];
    const uint32_t sA = smem_u32(smem);
    float* sMB = (float*)(smem + 2 * ABUF);

    const int t = threadIdx.x, l = t & 31, wid = t >> 5;
    const int b = blockIdx.x >> 5, mb = blockIdx.x & 31;
    const int wm = wid & 3, wn = wid >> 2;

    if (t < 256) sMB[t] = bias[t] * Berr[b * FOUT + t];

    // ---- A producer: thread t -> row t>>2, quarter-channel chunks of 8 ----
    const int row = t >> 2, q = t & 3;
    const uint32_t swz = (uint32_t)((row & 7) << 1);
    float4 xq0, xq1;                               // 8 f32 channels in flight

    auto loadQ = [&](int s, int j) {               // s = conv position 0..8
        int kh = s / 3, kw = s % 3;
        int y = mb * 2 + (row >> 6) + kh - 1;
        int x = (row & 63) + kw - 1;
        bool valid = ((unsigned)y < 64u) && ((unsigned)x < 64u);
        const float4* src = (const float4*)(X +
            (((size_t)b * 64 + (valid ? y : 0)) * 64 + (valid ? x : 0)) * CIN +
            j * 32 + q * 8);
        if (valid) { xq0 = src[0]; xq1 = src[1]; }
        else {
            float4 z = make_float4(0.f, 0.f, 0.f, 0.f);
            xq0 = z; xq1 = z;
        }
    };
    auto stsQ = [&](int j, int buf) {
        uint32_t h0, h1, h2, h3;
        asm volatile("cvt.rn.f16x2.f32 %0, %1, %2;" : "=r"(h0) : "f"(xq0.y), "f"(xq0.x));
        asm volatile("cvt.rn.f16x2.f32 %0, %1, %2;" : "=r"(h1) : "f"(xq0.w), "f"(xq0.z));
        asm volatile("cvt.rn.f16x2.f32 %0, %1, %2;" : "=r"(h2) : "f"(xq1.y), "f"(xq1.x));
        asm volatile("cvt.rn.f16x2.f32 %0, %1, %2;" : "=r"(h3) : "f"(xq1.w), "f"(xq1.z));
        uint32_t seg = (uint32_t)(j * 4 + q);
        uint32_t d = sA + (uint32_t)buf * ABUF + (uint32_t)row * 256u +
                     ((seg ^ swz) * 16u);
        asm volatile("st.shared.v4.b32 [%0], {%1,%2,%3,%4};"
                     :: "r"(d), "r"(h0), "r"(h1), "r"(h2), "r"(h3) : "memory");
    };

    // ---- consumer ldmatrix lane addressing ----
    const int lm = l >> 3, lri = l & 7;
    const int rowA0 = wm * 32 + lri + (lm & 1) * 8;   // + mt*16
    const uint32_t segHi = (uint32_t)(lm >> 1);       // 0: k0-7, 1: k8-15

    // ---- B fragment base pointer (uint4 units: 8 halves each) ----
    const uint4* bp = (const uint4*)g_wfrag +
                      (size_t)b * NG16 * 512 + wn * 128 + l;

    float acc[2][8][4];
#pragma unroll
    for (int mt = 0; mt < 2; mt++)
#pragma unroll
        for (int nt = 0; nt < 8; nt++)
#pragma unroll
            for (int qq = 0; qq < 4; qq++) acc[mt][nt][qq] = 0.f;

    // Prologue: stage 0 fully into buf0; B g=0 into regs
    loadQ(0, 0); stsQ(0, 0);
    loadQ(0, 1); stsQ(1, 0);
    loadQ(0, 2); stsQ(2, 0);
    loadQ(0, 3); stsQ(3, 0);
    uint4 bf[2][4];
#pragma unroll
    for (int qq = 0; qq < 4; qq++) bf[0][qq] = bp[qq * 32];
    __syncthreads();

    for (int s = 0; s < NPOS; s++) {
        const uint32_t abuf = sA + (uint32_t)(s & 1) * ABUF;
        const int nbuf = (s + 1) & 1;
        const bool more = (s + 1 < NPOS);

#pragma unroll
        for (int kk = 0; kk < 8; kk++) {          // eight k16 per 128-ch stage
            int g = s * 8 + kk;
            int gn = (g + 1 < NG16) ? g + 1 : g;
            uint4* nb = bf[(kk + 1) & 1];
#pragma unroll
            for (int qq = 0; qq < 4; qq++) nb[qq] = bp[(size_t)gn * 512 + qq * 32];

            // A fragments via ldmatrix.x4 (one per mt)
            uint32_t a[2][4];
            const uint32_t seg = (uint32_t)(kk * 2) + segHi;
#pragma unroll
            for (int mt = 0; mt < 2; mt++) {
                int rr = rowA0 + mt * 16;
                uint32_t addr = abuf + (uint32_t)rr * 256u +
                                ((seg ^ (uint32_t)((rr & 7) << 1)) * 16u);
                asm volatile("ldmatrix.sync.aligned.m8n8.x4.shared.b16 "
                             "{%0,%1,%2,%3}, [%4];"
                             : "=r"(a[mt][0]), "=r"(a[mt][1]),
                               "=r"(a[mt][2]), "=r"(a[mt][3])
                             : "r"(addr));
            }

            const uint4* cb = bf[kk & 1];
#pragma unroll
            for (int mt = 0; mt < 2; mt++)
#pragma unroll
                for (int nt = 0; nt < 8; nt++) {
                    const uint4 qv = cb[nt >> 1];
                    uint32_t b0, b1;
                    if (nt & 1) { b0 = qv.z; b1 = qv.w; }
                    else        { b0 = qv.x; b1 = qv.y; }
                    asm volatile(
                        "mma.sync.aligned.m16n8k16.row.col.f32.f16.f16.f32 "
                        "{%0,%1,%2,%3}, {%4,%5,%6,%7}, {%8,%9}, {%0,%1,%2,%3};"
                        : "+f"(acc[mt][nt][0]), "+f"(acc[mt][nt][1]),
                          "+f"(acc[mt][nt][2]), "+f"(acc[mt][nt][3])
                        : "r"(a[mt][0]), "r"(a[mt][1]), "r"(a[mt][2]), "r"(a[mt][3]),
                          "r"(b0), "r"(b1));
                }

            // ---- interleaved A producer for stage s+1 (quarters) ----
            if (more) {
                if (kk == 0) loadQ(s + 1, 0);
                if (kk == 2) { stsQ(0, nbuf); loadQ(s + 1, 1); }
                if (kk == 4) { stsQ(1, nbuf); loadQ(s + 1, 2); }
                if (kk == 6) { stsQ(2, nbuf); loadQ(s + 1, 3); }
            }
        }
        if (more) stsQ(3, nbuf);
        __syncthreads();
    }

    // ---- epilogue: bias + relu + float2 stores ----
#pragma unroll
    for (int mt = 0; mt < 2; mt++) {
        int pix = mb * 128 + wm * 32 + mt * 16 + (l >> 2);
        float* o = out + ((size_t)b * 4096 + pix) * FOUT;
#pragma unroll
        for (int nt = 0; nt < 8; nt++) {
            int f0 = wn * 64 + nt * 8 + (l & 3) * 2;
            float m0v = sMB[f0], m1v = sMB[f0 + 1];
            float2 r0, r1;
            r0.x = fmaxf(acc[mt][nt][0] + m0v, 0.f);
            r0.y = fmaxf(acc[mt][nt][1] + m1v, 0.f);
            r1.x = fmaxf(acc[mt][nt][2] + m0v, 0.f);
            r1.y = fmaxf(acc[mt][nt][3] + m1v, 0.f);
            *(float2*)(o + f0) = r0;
            *(float2*)(o + (size_t)8 * FOUT + f0) = r1;
        }
    }
}

// ============================================================================
// kernel_launch — size-match (elements or bytes) + positional fallback.
// ============================================================================
extern "C" void kernel_launch(void* const* d_in, const int* in_sizes, int n_in,
                              void* d_out, int out_size) {
    const long long EX = 33554432LL, EW = 294912LL, EBI = 256LL,
                    EWE = 9437184LL, EBE = 8192LL;

    auto pick = [&](long long elems) -> const float* {
        for (int i = 0; i < n_in; i++) {
            long long s = (long long)in_sizes[i];
            if (s == elems || s == elems * 4) return (const float*)d_in[i];
        }
        return nullptr;
    };
    const float* X    = pick(EX);
    const float* W    = pick(EW);
    const float* bias = pick(EBI);
    const float* Werr = pick(EWE);
    const float* Berr = pick(EBE);

    if (!X || !W || !bias || !Werr || !Berr) {
        if (n_in >= 5) {
            X    = (const float*)d_in[0];
            W    = (const float*)d_in[1];
            bias = (const float*)d_in[2];
            Werr = (const float*)d_in[3];
            Berr = (const float*)d_in[4];
        } else {
            return;
        }
    }

    float* out = (float*)d_out;

    cudaFuncSetAttribute(conv_main, cudaFuncAttributeMaxDynamicSharedMemorySize,
                         (int)SMEM_TOTAL);

    prep_wfrag<<<BATCH * 9, 256>>>(W, Werr);
    conv_main<<<BATCH * 32, 512, SMEM_TOTAL>>>(X, bias, Berr, out);
}

// round 11
// speedup vs baseline: 2.6731x; 1.1111x over previous
#include <cuda_runtime.h>
#include <cuda_fp16.h>
#include <cstdint>

// ============================================================================
// ConvAConnect: per-sample perturbed 3x3 SAME conv, B=32 H=W=64 Cin=128 F=256
// R11: 256-thread CTAs (CTA tile 64x256), 2 CTAs/SM to halve B fragment
// duplication (wm pair instead of quartet) and decorrelate barrier stalls.
// fp16 A in smem via ldmatrix, B fp16 fragment table register-prefetched
// from L2, interleaved producer, fp16 m16n8k16, f32 accumulate.
// ============================================================================
static constexpr int BATCH = 32;
static constexpr int CIN   = 128;
static constexpr int FOUT  = 256;
static constexpr int NG16  = 72;    // K=1152 / 16
static constexpr int NPOS  = 9;     // stages: one conv position = 128 ch each
static constexpr uint32_t ABUF = 16384;            // 64 rows x 256B fp16

// fp16 per-sample weights in exact m16n8k16 B-fragment order (same as R5-R10):
// half index = ((b*72 + g)*4 + wn)*1024 + q*256 + lane*8 + e*4 + r*2 + p
__device__ __align__(256) __half g_wfrag[(size_t)BATCH * NG16 * 4096];

__device__ __forceinline__ uint32_t smem_u32(const void* p) {
    uint32_t a;
    asm("{ .reg .u64 t; cvta.to.shared.u64 t, %1; cvt.u32.u64 %0, t; }" : "=r"(a) : "l"(p));
    return a;
}

// ============================================================================
// Prep: g_wfrag = frag_order(f16(W * Werr[b])). One block per (b, pos).
// ============================================================================
__global__ void __launch_bounds__(256) prep_wfrag(const float* __restrict__ W,
                                                  const float* __restrict__ Werr) {
    __shared__ float4 st4[512];                    // 8KB = 4096 halves
    __half* st = (__half*)st4;
    int blk = blockIdx.x;
    int b = blk / 9, pos = blk % 9;
    int f = threadIdx.x;                           // 0..255
    const float* wb = W    + (size_t)pos * CIN * FOUT + f;
    const float* eb = Werr + (size_t)(b * 9 + pos) * CIN * FOUT + f;
    const int wn = f >> 6, q = (f >> 4) & 3, e = (f >> 3) & 1;
    const int lane_base = (f & 7) * 4;

    for (int slab = 0; slab < 8; slab++) {         // 16 channels each
        __syncthreads();
#pragma unroll
        for (int ci = 0; ci < 16; ci++) {
            int c = slab * 16 + ci;
            float v = wb[(size_t)c * FOUT] * eb[(size_t)c * FOUT];
            int lane = lane_base + ((ci & 7) >> 1);
            int r = ci >> 3, p = ci & 1;
            st[wn * 1024 + q * 256 + lane * 8 + e * 4 + r * 2 + p] = __float2half_rn(v);
        }
        __syncthreads();
        int g = pos * 8 + slab;
        float4* dst = (float4*)(g_wfrag + (size_t)(b * NG16 + g) * 4096);
        dst[f * 2]     = st4[f * 2];
        dst[f * 2 + 1] = st4[f * 2 + 1];
    }
}

// ============================================================================
// Main: 2048 CTAs = 32 samples x 64 M-blocks (64 pixels = 1 image row each).
// 256 threads, 8 warps: wm = wid&1 (32-row half), wn = wid>>1 (64-col quarter).
// 2 CTAs/SM.
// ============================================================================
__global__ void __launch_bounds__(256, 2)
conv_main(const float* __restrict__ X, const float* __restrict__ bias,
          const float* __restrict__ Berr, float* __restrict__ out) {
    __shared__ float4 sAbuf[2048];                // 32KB: 2 stages x 16KB
    __shared__ float sMB[256];
    const uint32_t sA = smem_u32(sAbuf);

    const int t = threadIdx.x, l = t & 31, wid = t >> 5;
    const int b = blockIdx.x >> 6, mb = blockIdx.x & 63;
    const int wm = wid & 1, wn = wid >> 1;

    sMB[t] = bias[t] * Berr[b * FOUT + t];

    // ---- A producer: thread t -> row t>>2 (x pos), quarter chunks of 8 ch ----
    const int row = t >> 2, q = t & 3;
    const uint32_t swz = (uint32_t)((row & 7) << 1);
    float4 xq0, xq1;                               // 8 f32 channels in flight

    auto loadQ = [&](int s, int j) {               // s = conv position 0..8
        int kh = s / 3, kw = s % 3;
        int y = mb + kh - 1;
        int x = row + kw - 1;
        bool valid = ((unsigned)y < 64u) && ((unsigned)x < 64u);
        const float4* src = (const float4*)(X +
            (((size_t)b * 64 + (valid ? y : 0)) * 64 + (valid ? x : 0)) * CIN +
            j * 32 + q * 8);
        if (valid) { xq0 = src[0]; xq1 = src[1]; }
        else {
            float4 z = make_float4(0.f, 0.f, 0.f, 0.f);
            xq0 = z; xq1 = z;
        }
    };
    auto stsQ = [&](int j, int buf) {
        uint32_t h0, h1, h2, h3;
        asm volatile("cvt.rn.f16x2.f32 %0, %1, %2;" : "=r"(h0) : "f"(xq0.y), "f"(xq0.x));
        asm volatile("cvt.rn.f16x2.f32 %0, %1, %2;" : "=r"(h1) : "f"(xq0.w), "f"(xq0.z));
        asm volatile("cvt.rn.f16x2.f32 %0, %1, %2;" : "=r"(h2) : "f"(xq1.y), "f"(xq1.x));
        asm volatile("cvt.rn.f16x2.f32 %0, %1, %2;" : "=r"(h3) : "f"(xq1.w), "f"(xq1.z));
        uint32_t seg = (uint32_t)(j * 4 + q);
        uint32_t d = sA + (uint32_t)buf * ABUF + (uint32_t)row * 256u +
                     ((seg ^ swz) * 16u);
        asm volatile("st.shared.v4.b32 [%0], {%1,%2,%3,%4};"
                     :: "r"(d), "r"(h0), "r"(h1), "r"(h2), "r"(h3) : "memory");
    };

    // ---- consumer ldmatrix lane addressing ----
    const int lm = l >> 3, lri = l & 7;
    const int rowA0 = wm * 32 + lri + (lm & 1) * 8;   // + mt*16
    const uint32_t segHi = (uint32_t)(lm >> 1);       // 0: k0-7, 1: k8-15

    // ---- B fragment base pointer (uint4 units: 8 halves each) ----
    const uint4* bp = (const uint4*)g_wfrag +
                      (size_t)b * NG16 * 512 + wn * 128 + l;

    float acc[2][8][4];
#pragma unroll
    for (int mt = 0; mt < 2; mt++)
#pragma unroll
        for (int nt = 0; nt < 8; nt++)
#pragma unroll
            for (int qq = 0; qq < 4; qq++) acc[mt][nt][qq] = 0.f;

    // Prologue: stage 0 fully into buf0; B g=0 into regs
    loadQ(0, 0); stsQ(0, 0);
    loadQ(0, 1); stsQ(1, 0);
    loadQ(0, 2); stsQ(2, 0);
    loadQ(0, 3); stsQ(3, 0);
    uint4 bf[2][4];
#pragma unroll
    for (int qq = 0; qq < 4; qq++) bf[0][qq] = bp[qq * 32];
    __syncthreads();

    for (int s = 0; s < NPOS; s++) {
        const uint32_t abuf = sA + (uint32_t)(s & 1) * ABUF;
        const int nbuf = (s + 1) & 1;
        const bool more = (s + 1 < NPOS);

#pragma unroll
        for (int kk = 0; kk < 8; kk++) {          // eight k16 per 128-ch stage
            int g = s * 8 + kk;
            int gn = (g + 1 < NG16) ? g + 1 : g;
            uint4* nb = bf[(kk + 1) & 1];
#pragma unroll
            for (int qq = 0; qq < 4; qq++) nb[qq] = bp[(size_t)gn * 512 + qq * 32];

            // A fragments via ldmatrix.x4 (one per mt)
            uint32_t a[2][4];
            const uint32_t seg = (uint32_t)(kk * 2) + segHi;
#pragma unroll
            for (int mt = 0; mt < 2; mt++) {
                int rr = rowA0 + mt * 16;
                uint32_t addr = abuf + (uint32_t)rr * 256u +
                                ((seg ^ (uint32_t)((rr & 7) << 1)) * 16u);
                asm volatile("ldmatrix.sync.aligned.m8n8.x4.shared.b16 "
                             "{%0,%1,%2,%3}, [%4];"
                             : "=r"(a[mt][0]), "=r"(a[mt][1]),
                               "=r"(a[mt][2]), "=r"(a[mt][3])
                             : "r"(addr));
            }

            const uint4* cb = bf[kk & 1];
#pragma unroll
            for (int mt = 0; mt < 2; mt++)
#pragma unroll
                for (int nt = 0; nt < 8; nt++) {
                    const uint4 qv = cb[nt >> 1];
                    uint32_t b0, b1;
                    if (nt & 1) { b0 = qv.z; b1 = qv.w; }
                    else        { b0 = qv.x; b1 = qv.y; }
                    asm volatile(
                        "mma.sync.aligned.m16n8k16.row.col.f32.f16.f16.f32 "
                        "{%0,%1,%2,%3}, {%4,%5,%6,%7}, {%8,%9}, {%0,%1,%2,%3};"
                        : "+f"(acc[mt][nt][0]), "+f"(acc[mt][nt][1]),
                          "+f"(acc[mt][nt][2]), "+f"(acc[mt][nt][3])
                        : "r"(a[mt][0]), "r"(a[mt][1]), "r"(a[mt][2]), "r"(a[mt][3]),
                          "r"(b0), "r"(b1));
                }

            // ---- interleaved A producer for stage s+1 (quarters) ----
            if (more) {
                if (kk == 0) loadQ(s + 1, 0);
                if (kk == 2) { stsQ(0, nbuf); loadQ(s + 1, 1); }
                if (kk == 4) { stsQ(1, nbuf); loadQ(s + 1, 2); }
                if (kk == 6) { stsQ(2, nbuf); loadQ(s + 1, 3); }
            }
        }
        if (more) stsQ(3, nbuf);
        __syncthreads();
    }

    // ---- epilogue: bias + relu + float2 stores ----
#pragma unroll
    for (int mt = 0; mt < 2; mt++) {
        int pix = mb * 64 + wm * 32 + mt * 16 + (l >> 2);
        float* o = out + ((size_t)b * 4096 + pix) * FOUT;
#pragma unroll
        for (int nt = 0; nt < 8; nt++) {
            int f0 = wn * 64 + nt * 8 + (l & 3) * 2;
            float m0v = sMB[f0], m1v = sMB[f0 + 1];
            float2 r0, r1;
            r0.x = fmaxf(acc[mt][nt][0] + m0v, 0.f);
            r0.y = fmaxf(acc[mt][nt][1] + m1v, 0.f);
            r1.x = fmaxf(acc[mt][nt][2] + m0v, 0.f);
            r1.y = fmaxf(acc[mt][nt][3] + m1v, 0.f);
            *(float2*)(o + f0) = r0;
            *(float2*)(o + (size_t)8 * FOUT + f0) = r1;
        }
    }
}

// ============================================================================
// kernel_launch — size-match (elements or bytes) + positional fallback.
// ============================================================================
extern "C" void kernel_launch(void* const* d_in, const int* in_sizes, int n_in,
                              void* d_out, int out_size) {
    const long long EX = 33554432LL, EW = 294912LL, EBI = 256LL,
                    EWE = 9437184LL, EBE = 8192LL;

    auto pick = [&](long long elems) -> const float* {
        for (int i = 0; i < n_in; i++) {
            long long s = (long long)in_sizes[i];
            if (s == elems || s == elems * 4) return (const float*)d_in[i];
        }
        return nullptr;
    };
    const float* X    = pick(EX);
    const float* W    = pick(EW);
    const float* bias = pick(EBI);
    const float* Werr = pick(EWE);
    const float* Berr = pick(EBE);

    if (!X || !W || !bias || !Werr || !Berr) {
        if (n_in >= 5) {
            X    = (const float*)d_in[0];
            W    = (const float*)d_in[1];
            bias = (const float*)d_in[2];
            Werr = (const float*)d_in[3];
            Berr = (const float*)d_in[4];
        } else {
            return;
        }
    }

    float* out = (float*)d_out;

    prep_wfrag<<<BATCH * 9, 256>>>(W, Werr);
    conv_main<<<BATCH * 64, 256>>>(X, bias, Berr, out);
}

// round 12
// speedup vs baseline: 3.0339x; 1.1350x over previous
#include <cuda_runtime.h>
#include <cuda_fp16.h>
#include <cstdint>

// ============================================================================
// ConvAConnect: per-sample perturbed 3x3 SAME conv, B=32 H=W=64 Cin=128 F=256
// R12: R11 (256-thr CTAs, tile 64x256, 2 CTAs/SM) with
//  (1) conflict-free 3-bit rotated smem swizzle f(r)=((r&1)<<2)|((r>>1)&3)
//      -- removes the 2-way bank conflicts present in R8-R11 on LDSM and STS;
//  (2) B fragment prefetch distance 2 (same two buffers).
// fp16 m16n8k16, f32 accumulate; B fp16 fragment table in L2.
// ============================================================================
static constexpr int BATCH = 32;
static constexpr int CIN   = 128;
static constexpr int FOUT  = 256;
static constexpr int NG16  = 72;    // K=1152 / 16
static constexpr int NPOS  = 9;     // stages: one conv position = 128 ch each
static constexpr uint32_t ABUF = 16384;            // 64 rows x 256B fp16

// fp16 per-sample weights in exact m16n8k16 B-fragment order (same as R5-R11):
// half index = ((b*72 + g)*4 + wn)*1024 + q*256 + lane*8 + e*4 + r*2 + p
__device__ __align__(256) __half g_wfrag[(size_t)BATCH * NG16 * 4096];

__device__ __forceinline__ uint32_t smem_u32(const void* p) {
    uint32_t a;
    asm("{ .reg .u64 t; cvta.to.shared.u64 t, %1; cvt.u32.u64 %0, t; }" : "=r"(a) : "l"(p));
    return a;
}
// 3-bit row-rotation swizzle on the 16B-segment index: bijective per row,
// conflict-free for both producer STS.128 phases and consumer LDSM phases.
__device__ __forceinline__ uint32_t swz3(uint32_t r) {
    return ((r & 1u) << 2) | ((r >> 1) & 3u);
}

// ============================================================================
// Prep: g_wfrag = frag_order(f16(W * Werr[b])). One block per (b, pos).
// ============================================================================
__global__ void __launch_bounds__(256) prep_wfrag(const float* __restrict__ W,
                                                  const float* __restrict__ Werr) {
    __shared__ float4 st4[512];                    // 8KB = 4096 halves
    __half* st = (__half*)st4;
    int blk = blockIdx.x;
    int b = blk / 9, pos = blk % 9;
    int f = threadIdx.x;                           // 0..255
    const float* wb = W    + (size_t)pos * CIN * FOUT + f;
    const float* eb = Werr + (size_t)(b * 9 + pos) * CIN * FOUT + f;
    const int wn = f >> 6, q = (f >> 4) & 3, e = (f >> 3) & 1;
    const int lane_base = (f & 7) * 4;

    for (int slab = 0; slab < 8; slab++) {         // 16 channels each
        __syncthreads();
#pragma unroll
        for (int ci = 0; ci < 16; ci++) {
            int c = slab * 16 + ci;
            float v = wb[(size_t)c * FOUT] * eb[(size_t)c * FOUT];
            int lane = lane_base + ((ci & 7) >> 1);
            int r = ci >> 3, p = ci & 1;
            st[wn * 1024 + q * 256 + lane * 8 + e * 4 + r * 2 + p] = __float2half_rn(v);
        }
        __syncthreads();
        int g = pos * 8 + slab;
        float4* dst = (float4*)(g_wfrag + (size_t)(b * NG16 + g) * 4096);
        dst[f * 2]     = st4[f * 2];
        dst[f * 2 + 1] = st4[f * 2 + 1];
    }
}

// ============================================================================
// Main: 2048 CTAs = 32 samples x 64 M-blocks (64 pixels = 1 image row each).
// 256 threads, 8 warps: wm = wid&1 (32-row half), wn = wid>>1 (64-col quarter).
// 2 CTAs/SM.
// ============================================================================
__global__ void __launch_bounds__(256, 2)
conv_main(const float* __restrict__ X, const float* __restrict__ bias,
          const float* __restrict__ Berr, float* __restrict__ out) {
    __shared__ float4 sAbuf[2048];                // 32KB: 2 stages x 16KB
    __shared__ float sMB[256];
    const uint32_t sA = smem_u32(sAbuf);

    const int t = threadIdx.x, l = t & 31, wid = t >> 5;
    const int b = blockIdx.x >> 6, mb = blockIdx.x & 63;
    const int wm = wid & 1, wn = wid >> 1;

    sMB[t] = bias[t] * Berr[b * FOUT + t];

    // ---- A producer: thread t -> row t>>2 (x pos), quarter chunks of 8 ch ----
    const int row = t >> 2, q = t & 3;
    const uint32_t rsw = swz3((uint32_t)row);
    float4 xq0, xq1;                               // 8 f32 channels in flight

    auto loadQ = [&](int s, int j) {               // s = conv position 0..8
        int kh = s / 3, kw = s % 3;
        int y = mb + kh - 1;
        int x = row + kw - 1;
        bool valid = ((unsigned)y < 64u) && ((unsigned)x < 64u);
        const float4* src = (const float4*)(X +
            (((size_t)b * 64 + (valid ? y : 0)) * 64 + (valid ? x : 0)) * CIN +
            j * 32 + q * 8);
        if (valid) { xq0 = src[0]; xq1 = src[1]; }
        else {
            float4 z = make_float4(0.f, 0.f, 0.f, 0.f);
            xq0 = z; xq1 = z;
        }
    };
    auto stsQ = [&](int j, int buf) {
        uint32_t h0, h1, h2, h3;
        asm volatile("cvt.rn.f16x2.f32 %0, %1, %2;" : "=r"(h0) : "f"(xq0.y), "f"(xq0.x));
        asm volatile("cvt.rn.f16x2.f32 %0, %1, %2;" : "=r"(h1) : "f"(xq0.w), "f"(xq0.z));
        asm volatile("cvt.rn.f16x2.f32 %0, %1, %2;" : "=r"(h2) : "f"(xq1.y), "f"(xq1.x));
        asm volatile("cvt.rn.f16x2.f32 %0, %1, %2;" : "=r"(h3) : "f"(xq1.w), "f"(xq1.z));
        uint32_t seg = (uint32_t)(j * 4 + q);
        uint32_t d = sA + (uint32_t)buf * ABUF + (uint32_t)row * 256u +
                     ((seg ^ rsw) * 16u);
        asm volatile("st.shared.v4.b32 [%0], {%1,%2,%3,%4};"
                     :: "r"(d), "r"(h0), "r"(h1), "r"(h2), "r"(h3) : "memory");
    };

    // ---- consumer ldmatrix lane addressing ----
    const int lm = l >> 3, lri = l & 7;
    const int rowA0 = wm * 32 + lri + (lm & 1) * 8;   // + mt*16
    const uint32_t segHi = (uint32_t)(lm >> 1);       // 0: k0-7, 1: k8-15

    // ---- B fragment base pointer (uint4 units: 8 halves each) ----
    const uint4* bp = (const uint4*)g_wfrag +
                      (size_t)b * NG16 * 512 + wn * 128 + l;

    float acc[2][8][4];
#pragma unroll
    for (int mt = 0; mt < 2; mt++)
#pragma unroll
        for (int nt = 0; nt < 8; nt++)
#pragma unroll
            for (int qq = 0; qq < 4; qq++) acc[mt][nt][qq] = 0.f;

    // Prologue: stage 0 fully into buf0; B g=0 and g=1 into regs (distance 2)
    loadQ(0, 0); stsQ(0, 0);
    loadQ(0, 1); stsQ(1, 0);
    loadQ(0, 2); stsQ(2, 0);
    loadQ(0, 3); stsQ(3, 0);
    uint4 bf[2][4];
#pragma unroll
    for (int qq = 0; qq < 4; qq++) bf[0][qq] = bp[qq * 32];          // g = 0
#pragma unroll
    for (int qq = 0; qq < 4; qq++) bf[1][qq] = bp[512 + qq * 32];    // g = 1
    __syncthreads();

    for (int s = 0; s < NPOS; s++) {
        const uint32_t abuf = sA + (uint32_t)(s & 1) * ABUF;
        const int nbuf = (s + 1) & 1;
        const bool more = (s + 1 < NPOS);

#pragma unroll
        for (int kk = 0; kk < 8; kk++) {          // eight k16 per 128-ch stage
            int g = s * 8 + kk;

            // A fragments via ldmatrix.x4 (one per mt)
            uint32_t a[2][4];
            const uint32_t seg = (uint32_t)(kk * 2) + segHi;
#pragma unroll
            for (int mt = 0; mt < 2; mt++) {
                int rr = rowA0 + mt * 16;
                uint32_t addr = abuf + (uint32_t)rr * 256u +
                                ((seg ^ swz3((uint32_t)rr)) * 16u);
                asm volatile("ldmatrix.sync.aligned.m8n8.x4.shared.b16 "
                             "{%0,%1,%2,%3}, [%4];"
                             : "=r"(a[mt][0]), "=r"(a[mt][1]),
                               "=r"(a[mt][2]), "=r"(a[mt][3])
                             : "r"(addr));
            }

            const uint4* cb = bf[kk & 1];
#pragma unroll
            for (int mt = 0; mt < 2; mt++)
#pragma unroll
                for (int nt = 0; nt < 8; nt++) {
                    const uint4 qv = cb[nt >> 1];
                    uint32_t b0, b1;
                    if (nt & 1) { b0 = qv.z; b1 = qv.w; }
                    else        { b0 = qv.x; b1 = qv.y; }
                    asm volatile(
                        "mma.sync.aligned.m16n8k16.row.col.f32.f16.f16.f32 "
                        "{%0,%1,%2,%3}, {%4,%5,%6,%7}, {%8,%9}, {%0,%1,%2,%3};"
                        : "+f"(acc[mt][nt][0]), "+f"(acc[mt][nt][1]),
                          "+f"(acc[mt][nt][2]), "+f"(acc[mt][nt][3])
                        : "r"(a[mt][0]), "r"(a[mt][1]), "r"(a[mt][2]), "r"(a[mt][3]),
                          "r"(b0), "r"(b1));
                }

            // ---- refill consumed B buffer with g+2 (prefetch distance 2) ----
            {
                int gn = (g + 2 < NG16) ? g + 2 : g;
                uint4* nb = bf[kk & 1];
#pragma unroll
                for (int qq = 0; qq < 4; qq++) nb[qq] = bp[(size_t)gn * 512 + qq * 32];
            }

            // ---- interleaved A producer for stage s+1 (quarters) ----
            if (more) {
                if (kk == 0) loadQ(s + 1, 0);
                if (kk == 2) { stsQ(0, nbuf); loadQ(s + 1, 1); }
                if (kk == 4) { stsQ(1, nbuf); loadQ(s + 1, 2); }
                if (kk == 6) { stsQ(2, nbuf); loadQ(s + 1, 3); }
            }
        }
        if (more) stsQ(3, nbuf);
        __syncthreads();
    }

    // ---- epilogue: bias + relu + float2 stores ----
#pragma unroll
    for (int mt = 0; mt < 2; mt++) {
        int pix = mb * 64 + wm * 32 + mt * 16 + (l >> 2);
        float* o = out + ((size_t)b * 4096 + pix) * FOUT;
#pragma unroll
        for (int nt = 0; nt < 8; nt++) {
            int f0 = wn * 64 + nt * 8 + (l & 3) * 2;
            float m0v = sMB[f0], m1v = sMB[f0 + 1];
            float2 r0, r1;
            r0.x = fmaxf(acc[mt][nt][0] + m0v, 0.f);
            r0.y = fmaxf(acc[mt][nt][1] + m1v, 0.f);
            r1.x = fmaxf(acc[mt][nt][2] + m0v, 0.f);
            r1.y = fmaxf(acc[mt][nt][3] + m1v, 0.f);
            *(float2*)(o + f0) = r0;
            *(float2*)(o + (size_t)8 * FOUT + f0) = r1;
        }
    }
}

// ============================================================================
// kernel_launch — size-match (elements or bytes) + positional fallback.
// ============================================================================
extern "C" void kernel_launch(void* const* d_in, const int* in_sizes, int n_in,
                              void* d_out, int out_size) {
    const long long EX = 33554432LL, EW = 294912LL, EBI = 256LL,
                    EWE = 9437184LL, EBE = 8192LL;

    auto pick = [&](long long elems) -> const float* {
        for (int i = 0; i < n_in; i++) {
            long long s = (long long)in_sizes[i];
            if (s == elems || s == elems * 4) return (const float*)d_in[i];
        }
        return nullptr;
    };
    const float* X    = pick(EX);
    const float* W    = pick(EW);
    const float* bias = pick(EBI);
    const float* Werr = pick(EWE);
    const float* Berr = pick(EBE);

    if (!X || !W || !bias || !Werr || !Berr) {
        if (n_in >= 5) {
            X    = (const float*)d_in[0];
            W    = (const float*)d_in[1];
            bias = (const float*)d_in[2];
            Werr = (const float*)d_in[3];
            Berr = (const float*)d_in[4];
        } else {
            return;
        }
    }

    float* out = (float*)d_out;

    prep_wfrag<<<BATCH * 9, 256>>>(W, Werr);
    conv_main<<<BATCH * 64, 256>>>(X, bias, Berr, out);
}

// round 13
// speedup vs baseline: 3.3623x; 1.1082x over previous
#include <cuda_runtime.h>
#include <cuda_fp16.h>
#include <cstdint>

// ============================================================================
// ConvAConnect: per-sample perturbed 3x3 SAME conv, B=32 H=W=64 Cin=128 F=256
// R13: CTA tile 128x128 (pixels x filters), 128 threads, 4 warps of 64x64.
// Entire per-CTA X halo (4 image rows x 66 cols, fp16, zero-padded) loaded
// into smem ONCE; barrier-free mainloop of pure ldmatrix + B-LDG + HMMA.
// B fp16 fragment table in L2, prefetch distance 2. fp16 m16n8k16, f32 acc.
// ============================================================================
static constexpr int BATCH = 32;
static constexpr int CIN   = 128;
static constexpr int FOUT  = 256;
static constexpr int NG16  = 72;    // K=1152 / 16
static constexpr int HROWS = 4 * 66;               // halo rows (yy*66+xx)
static constexpr uint32_t SMEM_A   = 0;            // 264 rows x 256B = 67584
static constexpr uint32_t SMEM_MB  = 67584;        // 128 floats
static constexpr uint32_t SMEM_TOTAL = 67584 + 512;

// fp16 per-sample weights in exact m16n8k16 B-fragment order (same as R5-R12):
// half index = ((b*72 + g)*4 + wnq)*1024 + q*256 + lane*8 + e*4 + r*2 + p
__device__ __align__(256) __half g_wfrag[(size_t)BATCH * NG16 * 4096];

__device__ __forceinline__ uint32_t smem_u32(const void* p) {
    uint32_t a;
    asm("{ .reg .u64 t; cvta.to.shared.u64 t, %1; cvt.u32.u64 %0, t; }" : "=r"(a) : "l"(p));
    return a;
}
// 3-bit row-rotation swizzle on the 16B-segment index (conflict-free for
// LDSM octets over consecutive rows and for fill STS quarter-warps).
__device__ __forceinline__ uint32_t swz3(uint32_t r) {
    return ((r & 1u) << 2) | ((r >> 1) & 3u);
}

// ============================================================================
// Prep: g_wfrag = frag_order(f16(W * Werr[b])). One block per (b, pos).
// ============================================================================
__global__ void __launch_bounds__(256) prep_wfrag(const float* __restrict__ W,
                                                  const float* __restrict__ Werr) {
    __shared__ float4 st4[512];                    // 8KB = 4096 halves
    __half* st = (__half*)st4;
    int blk = blockIdx.x;
    int b = blk / 9, pos = blk % 9;
    int f = threadIdx.x;                           // 0..255
    const float* wb = W    + (size_t)pos * CIN * FOUT + f;
    const float* eb = Werr + (size_t)(b * 9 + pos) * CIN * FOUT + f;
    const int wn = f >> 6, q = (f >> 4) & 3, e = (f >> 3) & 1;
    const int lane_base = (f & 7) * 4;

    for (int slab = 0; slab < 8; slab++) {         // 16 channels each
        __syncthreads();
#pragma unroll
        for (int ci = 0; ci < 16; ci++) {
            int c = slab * 16 + ci;
            float v = wb[(size_t)c * FOUT] * eb[(size_t)c * FOUT];
            int lane = lane_base + ((ci & 7) >> 1);
            int r = ci >> 3, p = ci & 1;
            st[wn * 1024 + q * 256 + lane * 8 + e * 4 + r * 2 + p] = __float2half_rn(v);
        }
        __syncthreads();
        int g = pos * 8 + slab;
        float4* dst = (float4*)(g_wfrag + (size_t)(b * NG16 + g) * 4096);
        dst[f * 2]     = st4[f * 2];
        dst[f * 2 + 1] = st4[f * 2 + 1];
    }
}

// ============================================================================
// Main: 2048 CTAs = 32 b x 32 mb (128 px = 2 image rows) x 2 nb (128 f).
// 128 threads, 4 warps: wm = wid>>1 (64-px M half), wn = wid&1 (64-f half).
// ============================================================================
__global__ void __launch_bounds__(128, 2)
conv_main(const float* __restrict__ X, const float* __restrict__ bias,
          const float* __restrict__ Berr, float* __restrict__ out) {
    extern __shared__ char smem[];
    const uint32_t sA = smem_u32(smem);
    float* sMB = (float*)(smem + SMEM_MB);

    const int t = threadIdx.x, l = t & 31, wid = t >> 5;
    const int b  = blockIdx.x >> 6;
    const int mb = (blockIdx.x >> 1) & 31;
    const int nb = blockIdx.x & 1;
    const int wm = wid >> 1, wn = wid & 1;

    sMB[t] = bias[nb * 128 + t] * Berr[b * FOUT + nb * 128 + t];

    // ---- one-time X halo fill: rows r = yy*66+xx, fp16, zero-padded ----
    // warp per row; lane l covers channels l*4..l*4+3 (one float4 -> STS.64)
    for (int r = wid; r < HROWS; r += 4) {
        int yy = r / 66, xx = r - yy * 66;
        int y = mb * 2 - 1 + yy, x = xx - 1;
        bool valid = ((unsigned)y < 64u) && ((unsigned)x < 64u);
        float4 v = make_float4(0.f, 0.f, 0.f, 0.f);
        if (valid)
            v = ((const float4*)(X + (((size_t)b * 64 + y) * 64 + x) * CIN))[l];
        uint32_t h0, h1;
        asm volatile("cvt.rn.f16x2.f32 %0, %1, %2;" : "=r"(h0) : "f"(v.y), "f"(v.x));
        asm volatile("cvt.rn.f16x2.f32 %0, %1, %2;" : "=r"(h1) : "f"(v.w), "f"(v.z));
        uint32_t seg = (uint32_t)(l >> 1);
        uint32_t d = sA + (uint32_t)r * 256u + ((seg ^ swz3((uint32_t)r)) * 16u) +
                     (uint32_t)((l & 1) * 8);
        asm volatile("st.shared.v2.b32 [%0], {%1,%2};" :: "r"(d), "r"(h0), "r"(h1)
                     : "memory");
    }

    // ---- consumer ldmatrix lane addressing ----
    const int lm = l >> 3, lri = l & 7;
    const uint32_t segHi = (uint32_t)(lm >> 1);       // 0: k0-7, 1: k8-15
    int xb[4];                                        // x-offset per mt
#pragma unroll
    for (int mt = 0; mt < 4; mt++) xb[mt] = mt * 16 + lri + (lm & 1) * 8;

    // ---- B fragment base pointer (uint4 units: 8 halves each) ----
    const int wnq = nb * 2 + wn;                      // global f quarter
    const uint4* bp = (const uint4*)g_wfrag +
                      (size_t)b * NG16 * 512 + wnq * 128 + l;

    float acc[4][8][4];
#pragma unroll
    for (int mt = 0; mt < 4; mt++)
#pragma unroll
        for (int nt = 0; nt < 8; nt++)
#pragma unroll
            for (int qq = 0; qq < 4; qq++) acc[mt][nt][qq] = 0.f;

    // B prologue: g=0 and g=1 in regs (prefetch distance 2)
    uint4 bf[2][4];
#pragma unroll
    for (int qq = 0; qq < 4; qq++) bf[0][qq] = bp[qq * 32];
#pragma unroll
    for (int qq = 0; qq < 4; qq++) bf[1][qq] = bp[512 + qq * 32];
    __syncthreads();

    // ---- barrier-free mainloop: 9 positions x 8 k16 ----
    for (int s = 0; s < 9; s++) {
        int kh = s / 3, kw = s - kh * 3;
        const int rowoff = (wm + kh) * 66 + kw;       // smem halo row base

#pragma unroll
        for (int kk = 0; kk < 8; kk++) {
            int g = s * 8 + kk;

            // A fragments via ldmatrix.x4 (one per mt) from the halo
            uint32_t a[4][4];
            const uint32_t seg = (uint32_t)(kk * 2) + segHi;
#pragma unroll
            for (int mt = 0; mt < 4; mt++) {
                uint32_t rr = (uint32_t)(rowoff + xb[mt]);
                uint32_t addr = sA + rr * 256u + ((seg ^ swz3(rr)) * 16u);
                asm volatile("ldmatrix.sync.aligned.m8n8.x4.shared.b16 "
                             "{%0,%1,%2,%3}, [%4];"
                             : "=r"(a[mt][0]), "=r"(a[mt][1]),
                               "=r"(a[mt][2]), "=r"(a[mt][3])
                             : "r"(addr));
            }

            const uint4* cb = bf[kk & 1];
#pragma unroll
            for (int mt = 0; mt < 4; mt++)
#pragma unroll
                for (int nt = 0; nt < 8; nt++) {
                    const uint4 qv = cb[nt >> 1];
                    uint32_t b0, b1;
                    if (nt & 1) { b0 = qv.z; b1 = qv.w; }
                    else        { b0 = qv.x; b1 = qv.y; }
                    asm volatile(
                        "mma.sync.aligned.m16n8k16.row.col.f32.f16.f16.f32 "
                        "{%0,%1,%2,%3}, {%4,%5,%6,%7}, {%8,%9}, {%0,%1,%2,%3};"
                        : "+f"(acc[mt][nt][0]), "+f"(acc[mt][nt][1]),
                          "+f"(acc[mt][nt][2]), "+f"(acc[mt][nt][3])
                        : "r"(a[mt][0]), "r"(a[mt][1]), "r"(a[mt][2]), "r"(a[mt][3]),
                          "r"(b0), "r"(b1));
                }

            // refill consumed B buffer with g+2
            {
                int gn = (g + 2 < NG16) ? g + 2 : g;
                uint4* nbuf = bf[kk & 1];
#pragma unroll
                for (int qq = 0; qq < 4; qq++)
                    nbuf[qq] = bp[(size_t)gn * 512 + qq * 32];
            }
        }
    }

    // ---- epilogue: bias + relu + float2 stores ----
#pragma unroll
    for (int mt = 0; mt < 4; mt++) {
        int pix = mb * 128 + wm * 64 + mt * 16 + (l >> 2);
        float* o = out + ((size_t)b * 4096 + pix) * FOUT + nb * 128;
#pragma unroll
        for (int nt = 0; nt < 8; nt++) {
            int f0 = wn * 64 + nt * 8 + (l & 3) * 2;
            float m0v = sMB[f0], m1v = sMB[f0 + 1];
            float2 r0, r1;
            r0.x = fmaxf(acc[mt][nt][0] + m0v, 0.f);
            r0.y = fmaxf(acc[mt][nt][1] + m1v, 0.f);
            r1.x = fmaxf(acc[mt][nt][2] + m0v, 0.f);
            r1.y = fmaxf(acc[mt][nt][3] + m1v, 0.f);
            *(float2*)(o + f0) = r0;
            *(float2*)(o + (size_t)8 * FOUT + f0) = r1;
        }
    }
}

// ============================================================================
// kernel_launch — size-match (elements or bytes) + positional fallback.
// ============================================================================
extern "C" void kernel_launch(void* const* d_in, const int* in_sizes, int n_in,
                              void* d_out, int out_size) {
    const long long EX = 33554432LL, EW = 294912LL, EBI = 256LL,
                    EWE = 9437184LL, EBE = 8192LL;

    auto pick = [&](long long elems) -> const float* {
        for (int i = 0; i < n_in; i++) {
            long long s = (long long)in_sizes[i];
            if (s == elems || s == elems * 4) return (const float*)d_in[i];
        }
        return nullptr;
    };
    const float* X    = pick(EX);
    const float* W    = pick(EW);
    const float* bias = pick(EBI);
    const float* Werr = pick(EWE);
    const float* Berr = pick(EBE);

    if (!X || !W || !bias || !Werr || !Berr) {
        if (n_in >= 5) {
            X    = (const float*)d_in[0];
            W    = (const float*)d_in[1];
            bias = (const float*)d_in[2];
            Werr = (const float*)d_in[3];
            Berr = (const float*)d_in[4];
        } else {
            return;
        }
    }

    float* out = (float*)d_out;

    cudaFuncSetAttribute(conv_main, cudaFuncAttributeMaxDynamicSharedMemorySize,
                         (int)SMEM_TOTAL);

    prep_wfrag<<<BATCH * 9, 256>>>(W, Werr);
    conv_main<<<BATCH * 64, 128, SMEM_TOTAL>>>(X, bias, Berr, out);
}